// round 11
// baseline (speedup 1.0000x reference)
#include <cuda_runtime.h>
#include <cuda_bf16.h>
#include <cuda_fp16.h>
#include <math.h>
#include <stdint.h>

// Problem constants
#define T_SEQ 4096
#define C_DIM 768
#define NHEAD 12
#define HDIM  64
#define QKV3  (3 * C_DIM)

// ---------------------------------------------------------------------------
// Scratch (allocation-guard-safe device globals) — bf16 hi/lo split pairs
// (V region of qkv holds fp16 hi/lo instead; same storage size)
// ---------------------------------------------------------------------------
__device__ __nv_bfloat16 g_xh[(size_t)T_SEQ * C_DIM];
__device__ __nv_bfloat16 g_xl[(size_t)T_SEQ * C_DIM];
__device__ __nv_bfloat16 g_qkvh[(size_t)T_SEQ * QKV3];
__device__ __nv_bfloat16 g_qkvl[(size_t)T_SEQ * QKV3];
__device__ __nv_bfloat16 g_yh[(size_t)T_SEQ * C_DIM];
__device__ __nv_bfloat16 g_yl[(size_t)T_SEQ * C_DIM];
__device__ __nv_bfloat16 g_wqh[(size_t)QKV3 * C_DIM];   // W_qkv^T [3C][C]
__device__ __nv_bfloat16 g_wql[(size_t)QKV3 * C_DIM];
__device__ __nv_bfloat16 g_wph[(size_t)C_DIM * C_DIM];  // W_proj^T [C][C]
__device__ __nv_bfloat16 g_wpl[(size_t)C_DIM * C_DIM];

// ---------------------------------------------------------------------------
// MMA / ldmatrix / cp.async helpers (sm_80+ PTX; assembles on plain sm_103)
// ---------------------------------------------------------------------------
__device__ __forceinline__ uint32_t smem_u32(const void* p) {
    uint32_t a;
    asm("{ .reg .u64 t; cvta.to.shared.u64 t, %1; cvt.u32.u64 %0, t; }"
        : "=r"(a) : "l"(p));
    return a;
}
__device__ __forceinline__ void mma_bf16(float* c, const uint32_t* a,
                                         const uint32_t* b) {
    asm volatile(
        "mma.sync.aligned.m16n8k16.row.col.f32.bf16.bf16.f32 "
        "{%0,%1,%2,%3}, {%4,%5,%6,%7}, {%8,%9}, {%0,%1,%2,%3};"
        : "+f"(c[0]), "+f"(c[1]), "+f"(c[2]), "+f"(c[3])
        : "r"(a[0]), "r"(a[1]), "r"(a[2]), "r"(a[3]), "r"(b[0]), "r"(b[1]));
}
__device__ __forceinline__ void mma_f16(float* c, const uint32_t* a,
                                        const uint32_t* b) {
    asm volatile(
        "mma.sync.aligned.m16n8k16.row.col.f32.f16.f16.f32 "
        "{%0,%1,%2,%3}, {%4,%5,%6,%7}, {%8,%9}, {%0,%1,%2,%3};"
        : "+f"(c[0]), "+f"(c[1]), "+f"(c[2]), "+f"(c[3])
        : "r"(a[0]), "r"(a[1]), "r"(a[2]), "r"(a[3]), "r"(b[0]), "r"(b[1]));
}
__device__ __forceinline__ void ldsm_x4(uint32_t* r, uint32_t a) {
    asm volatile("ldmatrix.sync.aligned.m8n8.x4.shared.b16 {%0,%1,%2,%3}, [%4];"
                 : "=r"(r[0]), "=r"(r[1]), "=r"(r[2]), "=r"(r[3]) : "r"(a));
}
__device__ __forceinline__ void ldsm_x4_t(uint32_t* r, uint32_t a) {
    asm volatile("ldmatrix.sync.aligned.m8n8.x4.trans.shared.b16 {%0,%1,%2,%3}, [%4];"
                 : "=r"(r[0]), "=r"(r[1]), "=r"(r[2]), "=r"(r[3]) : "r"(a));
}
__device__ __forceinline__ void cp16(uint32_t dst, const void* src) {
    asm volatile("cp.async.cg.shared.global [%0], [%1], 16;"
                 :: "r"(dst), "l"(src));
}
#define CP_COMMIT() asm volatile("cp.async.commit_group;" ::: "memory")
#define CP_WAIT1()  asm volatile("cp.async.wait_group 1;" ::: "memory")
#define CP_WAIT0()  asm volatile("cp.async.wait_group 0;" ::: "memory")

// pack two f32 -> bf16x2 / f16x2 (first arg -> low half)
__device__ __forceinline__ uint32_t packbf(float lo, float hi) {
    uint32_t d;
    asm("cvt.rn.bf16x2.f32 %0, %1, %2;" : "=r"(d) : "f"(hi), "f"(lo));
    return d;
}
__device__ __forceinline__ uint32_t packhf(float lo, float hi) {
    uint32_t d;
    asm("cvt.rn.f16x2.f32 %0, %1, %2;" : "=r"(d) : "f"(hi), "f"(lo));
    return d;
}
__device__ __forceinline__ float lo_f(uint32_t u) { return __uint_as_float(u << 16); }
__device__ __forceinline__ float hi_f(uint32_t u) { return __uint_as_float(u & 0xffff0000u); }
__device__ __forceinline__ float lo_h(uint32_t u) {
    __half2 h = *reinterpret_cast<__half2*>(&u);
    return __half2float(h.x);
}
__device__ __forceinline__ float hi_h(uint32_t u) {
    __half2 h = *reinterpret_cast<__half2*>(&u);
    return __half2float(h.y);
}
__device__ __forceinline__ float ex2f(float x) {
    float y;
    asm("ex2.approx.f32 %0, %1;" : "=f"(y) : "f"(x));
    return y;
}

// byte offset into a [rows][64]-bf16 tile with chunk-XOR swizzle (16B chunks)
__device__ __forceinline__ uint32_t sw_off(int row, int chunk) {
    return (uint32_t)((row << 7) + (((chunk ^ row) & 7) << 4) + ((chunk & ~7) << 4));
}

// ---------------------------------------------------------------------------
// Prep: fp32 -> bf16 hi/lo split (float4 granularity)
// ---------------------------------------------------------------------------
__global__ __launch_bounds__(256) void split_f32(
    const float* __restrict__ X, __nv_bfloat16* __restrict__ Xh,
    __nv_bfloat16* __restrict__ Xl, int n4)
{
    int i = blockIdx.x * 256 + threadIdx.x;
    if (i >= n4) return;
    float4 x = reinterpret_cast<const float4*>(X)[i];
    uint32_t h0 = packbf(x.x, x.y);
    uint32_t h1 = packbf(x.z, x.w);
    uint32_t l0 = packbf(x.x - lo_f(h0), x.y - hi_f(h0));
    uint32_t l1 = packbf(x.z - lo_f(h1), x.w - hi_f(h1));
    reinterpret_cast<uint2*>(Xh)[i] = make_uint2(h0, h1);
    reinterpret_cast<uint2*>(Xl)[i] = make_uint2(l0, l1);
}

// ---------------------------------------------------------------------------
// Prep: W[K][N] -> Wt hi/lo [N][K]
// ---------------------------------------------------------------------------
__global__ __launch_bounds__(256) void transpose_split(
    const float* __restrict__ W, __nv_bfloat16* __restrict__ Th,
    __nv_bfloat16* __restrict__ Tl, int K, int N)
{
    __shared__ float tile[32][33];
    const int tx = threadIdx.x & 31;
    const int ty = threadIdx.x >> 5;
    const int n0 = blockIdx.x * 32;
    const int k0 = blockIdx.y * 32;
#pragma unroll
    for (int i = 0; i < 4; i++)
        tile[ty + 8 * i][tx] = W[(size_t)(k0 + ty + 8 * i) * N + n0 + tx];
    __syncthreads();
#pragma unroll
    for (int i = 0; i < 4; i++) {
        const float v = tile[tx][ty + 8 * i];
        const float h = __bfloat162float(__float2bfloat16_rn(v));
        const size_t o = (size_t)(n0 + ty + 8 * i) * K + k0 + tx;
        Th[o] = __float2bfloat16_rn(h);
        Tl[o] = __float2bfloat16_rn(v - h);
    }
}

// ---------------------------------------------------------------------------
// Split-bf16 HMMA GEMM, CTA 128x256, warp tile 64x64 (2m x 4n warps),
// k-chunk 64, 2-stage cp.async pipeline (96KB/stage, 1 barrier/iter).
// C[M,N] = (Ah+Al)[M,K] @ ((Bh+Bl)[N,K])^T + bias
// mode=1 (QKV): bf16 hi/lo out; Q cols scaled by 0.125*log2(e);
//               V cols (>=2C) written as fp16 hi/lo (for fp16 PV in attn).
// mode=0: fp32 out.  Requires N % 256 == 0.
// ---------------------------------------------------------------------------
#define GEMM_STAGE 98304
#define GEMM_SMEM (2 * GEMM_STAGE)
#define QSCALE 0.18033688011112042f   // 0.125 * log2(e)

__global__ __launch_bounds__(256) void gemm_mma(
    const __nv_bfloat16* __restrict__ Ah, const __nv_bfloat16* __restrict__ Al,
    const __nv_bfloat16* __restrict__ Bh, const __nv_bfloat16* __restrict__ Bl,
    const float* __restrict__ bias, float* __restrict__ Cf,
    __nv_bfloat16* __restrict__ Ch, __nv_bfloat16* __restrict__ Cl,
    int M, int N, int K, int mode)
{
    extern __shared__ char smb[];
    const uint32_t ubase = smem_u32(smb);

    const int tid = threadIdx.x;
    const int w = tid >> 5, lane = tid & 31;
    const int g = lane >> 2, t = lane & 3;
    const int wm = w & 1, wn = w >> 1;       // 2 m-strips x 4 n-strips
    const int by = blockIdx.y, bx = blockIdx.x;

    float acc[4][8][4];                       // mi (16 rows) x nb (8 cols)
#pragma unroll
    for (int mi = 0; mi < 4; mi++)
#pragma unroll
        for (int nb = 0; nb < 8; nb++)
#pragma unroll
            for (int c = 0; c < 4; c++) acc[mi][nb][c] = 0.0f;

    const int a_row = (lane & 15);
    const int a_chs = (lane >> 4);
    const int b_row = (lane & 7) + ((lane >> 4) << 3);
    const int b_chs = (lane >> 3) & 1;

    const int NI = K / 64;

    // stage layout: Ah 0 (16KB) | Al 16K | Bh 32K (32KB) | Bl 64K (32KB)
    auto load_stage = [&](int st, int k0) {
        const uint32_t ub = ubase + st * GEMM_STAGE;
#pragma unroll
        for (int j = 0; j < 4; j++) {         // A: 128 rows x 8 chunks
            const int i = tid + 256 * j;
            const int row = i >> 3, ch = i & 7;
            const size_t ga = (size_t)(by * 128 + row) * K + k0 + ch * 8;
            const uint32_t so = sw_off(row, ch);
            cp16(ub + so, Ah + ga);
            cp16(ub + 16384 + so, Al + ga);
        }
#pragma unroll
        for (int j = 0; j < 8; j++) {         // B: 256 rows x 8 chunks
            const int i = tid + 256 * j;
            const int row = i >> 3, ch = i & 7;
            const size_t gb = (size_t)(bx * 256 + row) * K + k0 + ch * 8;
            const uint32_t so = sw_off(row, ch);
            cp16(ub + 32768 + so, Bh + gb);
            cp16(ub + 65536 + so, Bl + gb);
        }
    };

    load_stage(0, 0);
    CP_COMMIT();

    for (int it = 0; it < NI; it++) {
        const int st = it & 1;
        CP_WAIT0();
        __syncthreads();
        if (it + 1 < NI) {
            load_stage(st ^ 1, (it + 1) * 64);
            CP_COMMIT();
        }

        const uint32_t uAh = ubase + st * GEMM_STAGE;
        const uint32_t uAl = uAh + 16384;
        const uint32_t uBh = uAh + 32768;
        const uint32_t uBl = uAh + 65536;

#pragma unroll
        for (int ks = 0; ks < 4; ks++) {
            uint32_t ah[4][4], al[4][4];
#pragma unroll
            for (int mi = 0; mi < 4; mi++) {
                const uint32_t so = sw_off(wm * 64 + mi * 16 + a_row, 2 * ks + a_chs);
                ldsm_x4(ah[mi], uAh + so);
                ldsm_x4(al[mi], uAl + so);
            }
#pragma unroll
            for (int nb = 0; nb < 8; nb += 2) {
                uint32_t bh4[4], bl4[4];
                const uint32_t so = sw_off(wn * 64 + nb * 8 + b_row, 2 * ks + b_chs);
                ldsm_x4(bh4, uBh + so);
                ldsm_x4(bl4, uBl + so);
#pragma unroll
                for (int mi = 0; mi < 4; mi++) {
                    mma_bf16(acc[mi][nb], ah[mi], bh4);
                    mma_bf16(acc[mi][nb], al[mi], bh4);
                    mma_bf16(acc[mi][nb], ah[mi], bl4);
                    mma_bf16(acc[mi][nb + 1], ah[mi], bh4 + 2);
                    mma_bf16(acc[mi][nb + 1], al[mi], bh4 + 2);
                    mma_bf16(acc[mi][nb + 1], ah[mi], bl4 + 2);
                }
            }
        }
    }

    // Epilogue
    const bool v_region = (mode == 1) && (bx * 256 >= 2 * C_DIM);  // V cols -> fp16
#pragma unroll
    for (int mi = 0; mi < 4; mi++) {
#pragma unroll
        for (int nb = 0; nb < 8; nb++) {
            const int row = by * 128 + wm * 64 + mi * 16 + g;
            const int col = bx * 256 + wn * 64 + nb * 8 + t * 2;
            const float2 bb = *reinterpret_cast<const float2*>(bias + col);
            float v0 = acc[mi][nb][0] + bb.x;
            float v1 = acc[mi][nb][1] + bb.y;
            float v2 = acc[mi][nb][2] + bb.x;
            float v3 = acc[mi][nb][3] + bb.y;
            if (mode) {
                uint32_t h0, l0, h1, l1;
                if (v_region) {
                    h0 = packhf(v0, v1);
                    l0 = packhf(v0 - lo_h(h0), v1 - hi_h(h0));
                    h1 = packhf(v2, v3);
                    l1 = packhf(v2 - lo_h(h1), v3 - hi_h(h1));
                } else {
                    const float sc = (col < C_DIM) ? QSCALE : 1.0f;  // Q -> log2 domain
                    v0 *= sc; v1 *= sc; v2 *= sc; v3 *= sc;
                    h0 = packbf(v0, v1);
                    l0 = packbf(v0 - lo_f(h0), v1 - hi_f(h0));
                    h1 = packbf(v2, v3);
                    l1 = packbf(v2 - lo_f(h1), v3 - hi_f(h1));
                }
                *reinterpret_cast<uint32_t*>(Ch + (size_t)row * N + col) = h0;
                *reinterpret_cast<uint32_t*>(Cl + (size_t)row * N + col) = l0;
                *reinterpret_cast<uint32_t*>(Ch + (size_t)(row + 8) * N + col) = h1;
                *reinterpret_cast<uint32_t*>(Cl + (size_t)(row + 8) * N + col) = l1;
            } else {
                *reinterpret_cast<float2*>(Cf + (size_t)row * N + col) =
                    make_float2(v0, v1);
                *reinterpret_cast<float2*>(Cf + (size_t)(row + 8) * N + col) =
                    make_float2(v2, v3);
            }
        }
    }
}

// ---------------------------------------------------------------------------
// Flash attention: S = split-bf16 3-term HMMA; PV = fp16 2-term with an
// all-ones constant B-fragment accumulating the softmax normalizer. 3-stage
// cp.async K/V pipeline, exp2-domain softmax, causal dead-block skipping.
// CTA = 128 q-rows x 1 head; 8 warps x 16 q-rows. P in registers (fp16).
// ---------------------------------------------------------------------------
#define ATT_SMEM (2 * 16384 + 3 * 4 * 16384)
#define ONES_F16X2 0x3C003C00u

__global__ __launch_bounds__(256, 1) void attn_mma(
    const __nv_bfloat16* __restrict__ qkvh, const __nv_bfloat16* __restrict__ qkvl,
    __nv_bfloat16* __restrict__ yh, __nv_bfloat16* __restrict__ yl)
{
    extern __shared__ char smb[];
    const uint32_t uQh = smem_u32(smb);
    const uint32_t uQl = uQh + 16384;
    const uint32_t uKV = uQh + 32768;   // stage s: +s*65536

    const int qb = 31 - (int)blockIdx.x;   // long CTAs first
    const int h = blockIdx.y;
    const int tid = threadIdx.x;
    const int w = tid >> 5, lane = tid & 31;
    const int g = lane >> 2, t = lane & 3;
    const int r0 = w * 16;

    const size_t qoff = (size_t)h * HDIM;
    const size_t koff = C_DIM + (size_t)h * HDIM;
    const size_t voff = 2 * C_DIM + (size_t)h * HDIM;

    auto load_kv = [&](int st, int kb) {
        const uint32_t ub = uKV + st * 65536;
#pragma unroll
        for (int j = 0; j < 4; j++) {
            const int i = tid + 256 * j;
            const int row = i >> 3, ch = i & 7;
            const size_t gk = (size_t)(kb * 128 + row) * QKV3 + koff + ch * 8;
            const size_t gv = (size_t)(kb * 128 + row) * QKV3 + voff + ch * 8;
            const uint32_t so = sw_off(row, ch);
            cp16(ub + so, qkvh + gk);
            cp16(ub + 16384 + so, qkvl + gk);
            cp16(ub + 32768 + so, qkvh + gv);
            cp16(ub + 49152 + so, qkvl + gv);
        }
    };

    // Prefetch K/V blocks 0 and 1, then load Q (regular STS) while DMA drains
    load_kv(0, 0);
    CP_COMMIT();
    if (qb >= 1) {
        load_kv(1, 1);
        CP_COMMIT();
    }
#pragma unroll 4
    for (int i = tid; i < 1024; i += 256) {
        const int row = i >> 3, ch = i & 7;
        const size_t gq = (size_t)(qb * 128 + row) * QKV3 + qoff + ch * 8;
        const uint32_t so = sw_off(row, ch);
        *reinterpret_cast<uint4*>(smb + so) =
            *reinterpret_cast<const uint4*>(qkvh + gq);
        *reinterpret_cast<uint4*>(smb + 16384 + so) =
            *reinterpret_cast<const uint4*>(qkvl + gq);
    }
    __syncthreads();

    // Q fragments (registers for the whole kernel); Q already in log2 domain
    uint32_t qfh[4][4], qfl[4][4];
    {
        const int arow = r0 + (lane & 15);
        const int achs = (lane >> 4);
#pragma unroll
        for (int ks = 0; ks < 4; ks++) {
            ldsm_x4(qfh[ks], uQh + sw_off(arow, 2 * ks + achs));
            ldsm_x4(qfl[ks], uQl + sw_off(arow, 2 * ks + achs));
        }
    }

    // o[0..7] = output dims; o[8] = softmax normalizer (ones-column block)
    float o[9][4];
#pragma unroll
    for (int nb = 0; nb < 9; nb++)
#pragma unroll
        for (int c = 0; c < 4; c++) o[nb][c] = 0.0f;
    float m0r = -INFINITY, m1r = -INFINITY;

    const uint32_t ones2[2] = { ONES_F16X2, ONES_F16X2 };

    const int b_row = (lane & 7) + ((lane >> 4) << 3);
    const int b_chs = (lane >> 3) & 1;
    const int v_row = (lane & 7) + (((lane >> 3) & 1) << 3);
    const int v_chs = (lane >> 4);

    for (int kb = 0; kb <= qb; kb++) {
        const int st = kb % 3;
        if (kb < qb) CP_WAIT1(); else CP_WAIT0();
        __syncthreads();

        // prefetch kb+2 into the stage last read at kb-1 (ordered by barrier)
        if (kb + 2 <= qb) {
            load_kv((kb + 2) % 3, kb + 2);
            CP_COMMIT();
        }

        const uint32_t uKh = uKV + st * 65536;
        const uint32_t uKl = uKh + 16384;
        const uint32_t uVh = uKh + 32768;
        const uint32_t uVl = uKh + 49152;

        // diagonal block: warp w only needs keys <= r0+15
        const bool diag = (kb == qb);
        const int nb_lim = diag ? 2 * (w + 1) : 16;  // S n-blocks needed
        const int kk_lim = diag ? (w + 1) : 8;       // PV k-chunks needed

        // ---- S = Q @ K^T (log2 domain; 16 n-blocks of 8 keys) ----
        float s[16][4];
#pragma unroll
        for (int nb = 0; nb < 16; nb++)
#pragma unroll
            for (int c = 0; c < 4; c++) s[nb][c] = 0.0f;

#pragma unroll
        for (int nb = 0; nb < 16; nb += 2) {
            if (nb < nb_lim) {
#pragma unroll
                for (int ks = 0; ks < 4; ks++) {
                    uint32_t kh4[4], kl4[4];
                    const uint32_t so = sw_off(nb * 8 + b_row, 2 * ks + b_chs);
                    ldsm_x4(kh4, uKh + so);
                    ldsm_x4(kl4, uKl + so);
                    mma_bf16(s[nb], qfh[ks], kh4);
                    mma_bf16(s[nb], qfl[ks], kh4);
                    mma_bf16(s[nb], qfh[ks], kl4);
                    mma_bf16(s[nb + 1], qfh[ks], kh4 + 2);
                    mma_bf16(s[nb + 1], qfl[ks], kh4 + 2);
                    mma_bf16(s[nb + 1], qfh[ks], kl4 + 2);
                }
            }
        }

        // ---- causal mask on the diagonal block ----
        if (diag) {
            const int ra = r0 + g, rb = r0 + g + 8;
#pragma unroll
            for (int nb = 0; nb < 16; nb++) {
                const int cb = nb * 8 + t * 2;
                if (cb > ra)     s[nb][0] = -1e30f;
                if (cb + 1 > ra) s[nb][1] = -1e30f;
                if (cb > rb)     s[nb][2] = -1e30f;
                if (cb + 1 > rb) s[nb][3] = -1e30f;
            }
        }

        // ---- online softmax in exp2 domain (rows g / g+8) ----
        float mx0 = -INFINITY, mx1 = -INFINITY;
#pragma unroll
        for (int nb = 0; nb < 16; nb++) {
            mx0 = fmaxf(mx0, fmaxf(s[nb][0], s[nb][1]));
            mx1 = fmaxf(mx1, fmaxf(s[nb][2], s[nb][3]));
        }
        mx0 = fmaxf(mx0, __shfl_xor_sync(0xffffffffu, mx0, 1));
        mx0 = fmaxf(mx0, __shfl_xor_sync(0xffffffffu, mx0, 2));
        mx1 = fmaxf(mx1, __shfl_xor_sync(0xffffffffu, mx1, 1));
        mx1 = fmaxf(mx1, __shfl_xor_sync(0xffffffffu, mx1, 2));
        const float mn0 = fmaxf(m0r, mx0);
        const float mn1 = fmaxf(m1r, mx1);
        const float c0 = ex2f(m0r - mn0);
        const float c1 = ex2f(m1r - mn1);
        m0r = mn0; m1r = mn1;
#pragma unroll
        for (int nb = 0; nb < 16; nb++) {
            s[nb][0] = ex2f(s[nb][0] - mn0);
            s[nb][1] = ex2f(s[nb][1] - mn0);
            s[nb][2] = ex2f(s[nb][2] - mn1);
            s[nb][3] = ex2f(s[nb][3] - mn1);
        }
        // rescale O and the normalizer block together
#pragma unroll
        for (int nb = 0; nb < 9; nb++) {
            o[nb][0] *= c0; o[nb][1] *= c0;
            o[nb][2] *= c1; o[nb][3] *= c1;
        }

        // ---- O += P @ V : P fp16 single, V fp16 hi/lo (2-term) + ones col ----
#pragma unroll
        for (int kk = 0; kk < 8; kk++) {
            if (kk < kk_lim) {
                uint32_t pf[4];
                pf[0] = packhf(s[2 * kk][0], s[2 * kk][1]);
                pf[1] = packhf(s[2 * kk][2], s[2 * kk][3]);
                pf[2] = packhf(s[2 * kk + 1][0], s[2 * kk + 1][1]);
                pf[3] = packhf(s[2 * kk + 1][2], s[2 * kk + 1][3]);
#pragma unroll
                for (int nb = 0; nb < 8; nb += 2) {
                    uint32_t vh4[4], vl4[4];
                    const uint32_t so = sw_off(kk * 16 + v_row, nb + v_chs);
                    ldsm_x4_t(vh4, uVh + so);
                    ldsm_x4_t(vl4, uVl + so);
                    mma_f16(o[nb], pf, vh4);
                    mma_f16(o[nb], pf, vl4);
                    mma_f16(o[nb + 1], pf, vh4 + 2);
                    mma_f16(o[nb + 1], pf, vl4 + 2);
                }
                mma_f16(o[8], pf, ones2);   // row sums of P -> normalizer
            }
        }
    }

    // ---- normalize and write y (bf16 hi/lo split) ----
    const float inv0 = 1.0f / o[8][0];
    const float inv1 = 1.0f / o[8][2];
    const int row0 = qb * 128 + r0 + g;
    const int row1 = row0 + 8;
#pragma unroll
    for (int nb = 0; nb < 8; nb++) {
        const int col = h * HDIM + nb * 8 + t * 2;
        float a0 = o[nb][0] * inv0, a1 = o[nb][1] * inv0;
        float b0 = o[nb][2] * inv1, b1 = o[nb][3] * inv1;
        uint32_t h0 = packbf(a0, a1);
        uint32_t l0 = packbf(a0 - lo_f(h0), a1 - hi_f(h0));
        uint32_t h1 = packbf(b0, b1);
        uint32_t l1 = packbf(b0 - lo_f(h1), b1 - hi_f(h1));
        *reinterpret_cast<uint32_t*>(yh + (size_t)row0 * C_DIM + col) = h0;
        *reinterpret_cast<uint32_t*>(yl + (size_t)row0 * C_DIM + col) = l0;
        *reinterpret_cast<uint32_t*>(yh + (size_t)row1 * C_DIM + col) = h1;
        *reinterpret_cast<uint32_t*>(yl + (size_t)row1 * C_DIM + col) = l1;
    }
}

// ---------------------------------------------------------------------------
// Launch
// ---------------------------------------------------------------------------
extern "C" void kernel_launch(void* const* d_in, const int* in_sizes, int n_in,
                              void* d_out, int out_size)
{
    (void)in_sizes; (void)n_in; (void)out_size;
    const float* x      = (const float*)d_in[0];
    const float* W_qkv  = (const float*)d_in[2];
    const float* b_qkv  = (const float*)d_in[3];
    const float* W_proj = (const float*)d_in[4];
    const float* b_proj = (const float*)d_in[5];
    float* out = (float*)d_out;

    __nv_bfloat16 *xh, *xl, *qkvh, *qkvl, *yh, *yl, *wqh, *wql, *wph, *wpl;
    cudaGetSymbolAddress((void**)&xh, g_xh);
    cudaGetSymbolAddress((void**)&xl, g_xl);
    cudaGetSymbolAddress((void**)&qkvh, g_qkvh);
    cudaGetSymbolAddress((void**)&qkvl, g_qkvl);
    cudaGetSymbolAddress((void**)&yh, g_yh);
    cudaGetSymbolAddress((void**)&yl, g_yl);
    cudaGetSymbolAddress((void**)&wqh, g_wqh);
    cudaGetSymbolAddress((void**)&wql, g_wql);
    cudaGetSymbolAddress((void**)&wph, g_wph);
    cudaGetSymbolAddress((void**)&wpl, g_wpl);

    cudaFuncSetAttribute(gemm_mma,
                         cudaFuncAttributeMaxDynamicSharedMemorySize, GEMM_SMEM);
    cudaFuncSetAttribute(attn_mma,
                         cudaFuncAttributeMaxDynamicSharedMemorySize, ATT_SMEM);

    // 0) prep: weight transpose+split, input split
    transpose_split<<<dim3(QKV3 / 32, C_DIM / 32), 256>>>(
        W_qkv, wqh, wql, C_DIM, QKV3);
    transpose_split<<<dim3(C_DIM / 32, C_DIM / 32), 256>>>(
        W_proj, wph, wpl, C_DIM, C_DIM);
    split_f32<<<(T_SEQ * C_DIM / 4 + 255) / 256, 256>>>(
        x, xh, xl, T_SEQ * C_DIM / 4);

    // 1) qkv = x @ W_qkv + b_qkv; Q -> log2 domain bf16, K bf16, V fp16 splits
    gemm_mma<<<dim3(QKV3 / 256, T_SEQ / 128), 256, GEMM_SMEM>>>(
        xh, xl, wqh, wql, b_qkv, nullptr, qkvh, qkvl, T_SEQ, QKV3, C_DIM, 1);

    // 2) y = causal_attention(qkv) -> bf16 hi/lo
    attn_mma<<<dim3(T_SEQ / 128, NHEAD), 256, ATT_SMEM>>>(qkvh, qkvl, yh, yl);

    // 3) out = y @ W_proj + b_proj (fp32)
    gemm_mma<<<dim3(C_DIM / 256, T_SEQ / 128), 256, GEMM_SMEM>>>(
        yh, yl, wph, wpl, b_proj, out, nullptr, nullptr, T_SEQ, C_DIM, C_DIM, 0);
}

// round 12
// speedup vs baseline: 1.1529x; 1.1529x over previous
#include <cuda_runtime.h>
#include <cuda_bf16.h>
#include <cuda_fp16.h>
#include <math.h>
#include <stdint.h>

// Problem constants
#define T_SEQ 4096
#define C_DIM 768
#define NHEAD 12
#define HDIM  64
#define QKV3  (3 * C_DIM)

// ---------------------------------------------------------------------------
// Scratch (allocation-guard-safe device globals) — bf16 hi/lo split pairs
// (V region of qkv holds fp16; only the hi plane is used for V)
// ---------------------------------------------------------------------------
__device__ __nv_bfloat16 g_xh[(size_t)T_SEQ * C_DIM];
__device__ __nv_bfloat16 g_xl[(size_t)T_SEQ * C_DIM];
__device__ __nv_bfloat16 g_qkvh[(size_t)T_SEQ * QKV3];
__device__ __nv_bfloat16 g_qkvl[(size_t)T_SEQ * QKV3];
__device__ __nv_bfloat16 g_yh[(size_t)T_SEQ * C_DIM];
__device__ __nv_bfloat16 g_yl[(size_t)T_SEQ * C_DIM];
__device__ __nv_bfloat16 g_wqh[(size_t)QKV3 * C_DIM];   // W_qkv^T [3C][C]
__device__ __nv_bfloat16 g_wql[(size_t)QKV3 * C_DIM];
__device__ __nv_bfloat16 g_wph[(size_t)C_DIM * C_DIM];  // W_proj^T [C][C]
__device__ __nv_bfloat16 g_wpl[(size_t)C_DIM * C_DIM];

// ---------------------------------------------------------------------------
// MMA / ldmatrix / cp.async helpers (sm_80+ PTX; assembles on plain sm_103)
// ---------------------------------------------------------------------------
__device__ __forceinline__ uint32_t smem_u32(const void* p) {
    uint32_t a;
    asm("{ .reg .u64 t; cvta.to.shared.u64 t, %1; cvt.u32.u64 %0, t; }"
        : "=r"(a) : "l"(p));
    return a;
}
__device__ __forceinline__ void mma_bf16(float* c, const uint32_t* a,
                                         const uint32_t* b) {
    asm volatile(
        "mma.sync.aligned.m16n8k16.row.col.f32.bf16.bf16.f32 "
        "{%0,%1,%2,%3}, {%4,%5,%6,%7}, {%8,%9}, {%0,%1,%2,%3};"
        : "+f"(c[0]), "+f"(c[1]), "+f"(c[2]), "+f"(c[3])
        : "r"(a[0]), "r"(a[1]), "r"(a[2]), "r"(a[3]), "r"(b[0]), "r"(b[1]));
}
__device__ __forceinline__ void mma_f16(float* c, const uint32_t* a,
                                        const uint32_t* b) {
    asm volatile(
        "mma.sync.aligned.m16n8k16.row.col.f32.f16.f16.f32 "
        "{%0,%1,%2,%3}, {%4,%5,%6,%7}, {%8,%9}, {%0,%1,%2,%3};"
        : "+f"(c[0]), "+f"(c[1]), "+f"(c[2]), "+f"(c[3])
        : "r"(a[0]), "r"(a[1]), "r"(a[2]), "r"(a[3]), "r"(b[0]), "r"(b[1]));
}
__device__ __forceinline__ void ldsm_x4(uint32_t* r, uint32_t a) {
    asm volatile("ldmatrix.sync.aligned.m8n8.x4.shared.b16 {%0,%1,%2,%3}, [%4];"
                 : "=r"(r[0]), "=r"(r[1]), "=r"(r[2]), "=r"(r[3]) : "r"(a));
}
__device__ __forceinline__ void ldsm_x4_t(uint32_t* r, uint32_t a) {
    asm volatile("ldmatrix.sync.aligned.m8n8.x4.trans.shared.b16 {%0,%1,%2,%3}, [%4];"
                 : "=r"(r[0]), "=r"(r[1]), "=r"(r[2]), "=r"(r[3]) : "r"(a));
}
__device__ __forceinline__ void cp16(uint32_t dst, const void* src) {
    asm volatile("cp.async.cg.shared.global [%0], [%1], 16;"
                 :: "r"(dst), "l"(src));
}
#define CP_COMMIT() asm volatile("cp.async.commit_group;" ::: "memory")
#define CP_WAIT1()  asm volatile("cp.async.wait_group 1;" ::: "memory")
#define CP_WAIT0()  asm volatile("cp.async.wait_group 0;" ::: "memory")

// pack two f32 -> bf16x2 / f16x2 (first arg -> low half)
__device__ __forceinline__ uint32_t packbf(float lo, float hi) {
    uint32_t d;
    asm("cvt.rn.bf16x2.f32 %0, %1, %2;" : "=r"(d) : "f"(hi), "f"(lo));
    return d;
}
__device__ __forceinline__ uint32_t packhf(float lo, float hi) {
    uint32_t d;
    asm("cvt.rn.f16x2.f32 %0, %1, %2;" : "=r"(d) : "f"(hi), "f"(lo));
    return d;
}
__device__ __forceinline__ float lo_f(uint32_t u) { return __uint_as_float(u << 16); }
__device__ __forceinline__ float hi_f(uint32_t u) { return __uint_as_float(u & 0xffff0000u); }
__device__ __forceinline__ float ex2f(float x) {
    float y;
    asm("ex2.approx.f32 %0, %1;" : "=f"(y) : "f"(x));
    return y;
}

// byte offset into a [rows][64]-bf16 tile with chunk-XOR swizzle (16B chunks)
__device__ __forceinline__ uint32_t sw_off(int row, int chunk) {
    return (uint32_t)((row << 7) + (((chunk ^ row) & 7) << 4) + ((chunk & ~7) << 4));
}

// ---------------------------------------------------------------------------
// Prep: fp32 -> bf16 hi/lo split (float4 granularity)
// ---------------------------------------------------------------------------
__global__ __launch_bounds__(256) void split_f32(
    const float* __restrict__ X, __nv_bfloat16* __restrict__ Xh,
    __nv_bfloat16* __restrict__ Xl, int n4)
{
    int i = blockIdx.x * 256 + threadIdx.x;
    if (i >= n4) return;
    float4 x = reinterpret_cast<const float4*>(X)[i];
    uint32_t h0 = packbf(x.x, x.y);
    uint32_t h1 = packbf(x.z, x.w);
    uint32_t l0 = packbf(x.x - lo_f(h0), x.y - hi_f(h0));
    uint32_t l1 = packbf(x.z - lo_f(h1), x.w - hi_f(h1));
    reinterpret_cast<uint2*>(Xh)[i] = make_uint2(h0, h1);
    reinterpret_cast<uint2*>(Xl)[i] = make_uint2(l0, l1);
}

// ---------------------------------------------------------------------------
// Prep: W[K][N] -> Wt hi/lo [N][K]
// ---------------------------------------------------------------------------
__global__ __launch_bounds__(256) void transpose_split(
    const float* __restrict__ W, __nv_bfloat16* __restrict__ Th,
    __nv_bfloat16* __restrict__ Tl, int K, int N)
{
    __shared__ float tile[32][33];
    const int tx = threadIdx.x & 31;
    const int ty = threadIdx.x >> 5;
    const int n0 = blockIdx.x * 32;
    const int k0 = blockIdx.y * 32;
#pragma unroll
    for (int i = 0; i < 4; i++)
        tile[ty + 8 * i][tx] = W[(size_t)(k0 + ty + 8 * i) * N + n0 + tx];
    __syncthreads();
#pragma unroll
    for (int i = 0; i < 4; i++) {
        const float v = tile[tx][ty + 8 * i];
        const float h = __bfloat162float(__float2bfloat16_rn(v));
        const size_t o = (size_t)(n0 + ty + 8 * i) * K + k0 + tx;
        Th[o] = __float2bfloat16_rn(h);
        Tl[o] = __float2bfloat16_rn(v - h);
    }
}

// ---------------------------------------------------------------------------
// Split-bf16 HMMA GEMM, CTA 128x256, warp tile 64x64 (2m x 4n warps),
// k-chunk 64, 2-stage cp.async pipeline (96KB/stage, 1 barrier/iter).
// C[M,N] = (Ah+Al)[M,K] @ ((Bh+Bl)[N,K])^T + bias
// mode=1 (QKV): bf16 hi/lo out; Q cols scaled by 0.125*log2(e);
//               V cols (>=2C) written as fp16 (hi plane used by attention).
// mode=0: fp32 out.  Requires N % 256 == 0.
// ---------------------------------------------------------------------------
#define GEMM_STAGE 98304
#define GEMM_SMEM (2 * GEMM_STAGE)
#define QSCALE 0.18033688011112042f   // 0.125 * log2(e)

__global__ __launch_bounds__(256) void gemm_mma(
    const __nv_bfloat16* __restrict__ Ah, const __nv_bfloat16* __restrict__ Al,
    const __nv_bfloat16* __restrict__ Bh, const __nv_bfloat16* __restrict__ Bl,
    const float* __restrict__ bias, float* __restrict__ Cf,
    __nv_bfloat16* __restrict__ Ch, __nv_bfloat16* __restrict__ Cl,
    int M, int N, int K, int mode)
{
    extern __shared__ char smb[];
    const uint32_t ubase = smem_u32(smb);

    const int tid = threadIdx.x;
    const int w = tid >> 5, lane = tid & 31;
    const int g = lane >> 2, t = lane & 3;
    const int wm = w & 1, wn = w >> 1;       // 2 m-strips x 4 n-strips
    const int by = blockIdx.y, bx = blockIdx.x;

    float acc[4][8][4];                       // mi (16 rows) x nb (8 cols)
#pragma unroll
    for (int mi = 0; mi < 4; mi++)
#pragma unroll
        for (int nb = 0; nb < 8; nb++)
#pragma unroll
            for (int c = 0; c < 4; c++) acc[mi][nb][c] = 0.0f;

    const int a_row = (lane & 15);
    const int a_chs = (lane >> 4);
    const int b_row = (lane & 7) + ((lane >> 4) << 3);
    const int b_chs = (lane >> 3) & 1;

    const int NI = K / 64;

    // stage layout: Ah 0 (16KB) | Al 16K | Bh 32K (32KB) | Bl 64K (32KB)
    auto load_stage = [&](int st, int k0) {
        const uint32_t ub = ubase + st * GEMM_STAGE;
#pragma unroll
        for (int j = 0; j < 4; j++) {         // A: 128 rows x 8 chunks
            const int i = tid + 256 * j;
            const int row = i >> 3, ch = i & 7;
            const size_t ga = (size_t)(by * 128 + row) * K + k0 + ch * 8;
            const uint32_t so = sw_off(row, ch);
            cp16(ub + so, Ah + ga);
            cp16(ub + 16384 + so, Al + ga);
        }
#pragma unroll
        for (int j = 0; j < 8; j++) {         // B: 256 rows x 8 chunks
            const int i = tid + 256 * j;
            const int row = i >> 3, ch = i & 7;
            const size_t gb = (size_t)(bx * 256 + row) * K + k0 + ch * 8;
            const uint32_t so = sw_off(row, ch);
            cp16(ub + 32768 + so, Bh + gb);
            cp16(ub + 65536 + so, Bl + gb);
        }
    };

    load_stage(0, 0);
    CP_COMMIT();

    for (int it = 0; it < NI; it++) {
        const int st = it & 1;
        CP_WAIT0();
        __syncthreads();
        if (it + 1 < NI) {
            load_stage(st ^ 1, (it + 1) * 64);
            CP_COMMIT();
        }

        const uint32_t uAh = ubase + st * GEMM_STAGE;
        const uint32_t uAl = uAh + 16384;
        const uint32_t uBh = uAh + 32768;
        const uint32_t uBl = uAh + 65536;

#pragma unroll
        for (int ks = 0; ks < 4; ks++) {
            uint32_t ah[4][4], al[4][4];
#pragma unroll
            for (int mi = 0; mi < 4; mi++) {
                const uint32_t so = sw_off(wm * 64 + mi * 16 + a_row, 2 * ks + a_chs);
                ldsm_x4(ah[mi], uAh + so);
                ldsm_x4(al[mi], uAl + so);
            }
#pragma unroll
            for (int nb = 0; nb < 8; nb += 2) {
                uint32_t bh4[4], bl4[4];
                const uint32_t so = sw_off(wn * 64 + nb * 8 + b_row, 2 * ks + b_chs);
                ldsm_x4(bh4, uBh + so);
                ldsm_x4(bl4, uBl + so);
#pragma unroll
                for (int mi = 0; mi < 4; mi++) {
                    mma_bf16(acc[mi][nb], ah[mi], bh4);
                    mma_bf16(acc[mi][nb], al[mi], bh4);
                    mma_bf16(acc[mi][nb], ah[mi], bl4);
                    mma_bf16(acc[mi][nb + 1], ah[mi], bh4 + 2);
                    mma_bf16(acc[mi][nb + 1], al[mi], bh4 + 2);
                    mma_bf16(acc[mi][nb + 1], ah[mi], bl4 + 2);
                }
            }
        }
    }

    // Epilogue
    const bool v_region = (mode == 1) && (bx * 256 >= 2 * C_DIM);  // V cols -> fp16
#pragma unroll
    for (int mi = 0; mi < 4; mi++) {
#pragma unroll
        for (int nb = 0; nb < 8; nb++) {
            const int row = by * 128 + wm * 64 + mi * 16 + g;
            const int col = bx * 256 + wn * 64 + nb * 8 + t * 2;
            const float2 bb = *reinterpret_cast<const float2*>(bias + col);
            float v0 = acc[mi][nb][0] + bb.x;
            float v1 = acc[mi][nb][1] + bb.y;
            float v2 = acc[mi][nb][2] + bb.x;
            float v3 = acc[mi][nb][3] + bb.y;
            if (mode) {
                if (v_region) {
                    // V: single fp16 (hi plane only; attention ignores lo)
                    *reinterpret_cast<uint32_t*>(Ch + (size_t)row * N + col) =
                        packhf(v0, v1);
                    *reinterpret_cast<uint32_t*>(Ch + (size_t)(row + 8) * N + col) =
                        packhf(v2, v3);
                } else {
                    const float sc = (col < C_DIM) ? QSCALE : 1.0f;  // Q -> log2 domain
                    v0 *= sc; v1 *= sc; v2 *= sc; v3 *= sc;
                    uint32_t h0 = packbf(v0, v1);
                    uint32_t l0 = packbf(v0 - lo_f(h0), v1 - hi_f(h0));
                    uint32_t h1 = packbf(v2, v3);
                    uint32_t l1 = packbf(v2 - lo_f(h1), v3 - hi_f(h1));
                    *reinterpret_cast<uint32_t*>(Ch + (size_t)row * N + col) = h0;
                    *reinterpret_cast<uint32_t*>(Cl + (size_t)row * N + col) = l0;
                    *reinterpret_cast<uint32_t*>(Ch + (size_t)(row + 8) * N + col) = h1;
                    *reinterpret_cast<uint32_t*>(Cl + (size_t)(row + 8) * N + col) = l1;
                }
            } else {
                *reinterpret_cast<float2*>(Cf + (size_t)row * N + col) =
                    make_float2(v0, v1);
                *reinterpret_cast<float2*>(Cf + (size_t)(row + 8) * N + col) =
                    make_float2(v2, v3);
            }
        }
    }
}

// ---------------------------------------------------------------------------
// Flash attention: S = split-bf16 3-term HMMA; PV = single-fp16 1-term with
// an all-ones constant B-fragment accumulating the softmax normalizer.
// 3-stage cp.async K/V pipeline (48KB/stage), exp2-domain softmax.
// CTA = 128 q-rows x 1 head; 8 warps x 16 q-rows. P in registers (fp16).
// ---------------------------------------------------------------------------
#define ATT_STAGE 49152
#define ATT_SMEM (2 * 16384 + 3 * ATT_STAGE)
#define ONES_F16X2 0x3C003C00u

__global__ __launch_bounds__(256, 1) void attn_mma(
    const __nv_bfloat16* __restrict__ qkvh, const __nv_bfloat16* __restrict__ qkvl,
    __nv_bfloat16* __restrict__ yh, __nv_bfloat16* __restrict__ yl)
{
    extern __shared__ char smb[];
    const uint32_t uQh = smem_u32(smb);
    const uint32_t uQl = uQh + 16384;
    const uint32_t uKV = uQh + 32768;   // stage s: +s*ATT_STAGE (Kh|Kl|Vh)

    const int qb = 31 - (int)blockIdx.x;   // long CTAs first
    const int h = blockIdx.y;
    const int tid = threadIdx.x;
    const int w = tid >> 5, lane = tid & 31;
    const int g = lane >> 2, t = lane & 3;
    const int r0 = w * 16;

    const size_t qoff = (size_t)h * HDIM;
    const size_t koff = C_DIM + (size_t)h * HDIM;
    const size_t voff = 2 * C_DIM + (size_t)h * HDIM;

    auto load_kv = [&](int st, int kb) {
        const uint32_t ub = uKV + st * ATT_STAGE;
#pragma unroll
        for (int j = 0; j < 4; j++) {
            const int i = tid + 256 * j;
            const int row = i >> 3, ch = i & 7;
            const size_t gk = (size_t)(kb * 128 + row) * QKV3 + koff + ch * 8;
            const size_t gv = (size_t)(kb * 128 + row) * QKV3 + voff + ch * 8;
            const uint32_t so = sw_off(row, ch);
            cp16(ub + so, qkvh + gk);
            cp16(ub + 16384 + so, qkvl + gk);
            cp16(ub + 32768 + so, qkvh + gv);
        }
    };

    // Prefetch K/V blocks 0 and 1, then load Q (regular STS) while DMA drains
    load_kv(0, 0);
    CP_COMMIT();
    if (qb >= 1) {
        load_kv(1, 1);
        CP_COMMIT();
    }
#pragma unroll 4
    for (int i = tid; i < 1024; i += 256) {
        const int row = i >> 3, ch = i & 7;
        const size_t gq = (size_t)(qb * 128 + row) * QKV3 + qoff + ch * 8;
        const uint32_t so = sw_off(row, ch);
        *reinterpret_cast<uint4*>(smb + so) =
            *reinterpret_cast<const uint4*>(qkvh + gq);
        *reinterpret_cast<uint4*>(smb + 16384 + so) =
            *reinterpret_cast<const uint4*>(qkvl + gq);
    }
    __syncthreads();

    // Q fragments (registers for the whole kernel); Q already in log2 domain
    uint32_t qfh[4][4], qfl[4][4];
    {
        const int arow = r0 + (lane & 15);
        const int achs = (lane >> 4);
#pragma unroll
        for (int ks = 0; ks < 4; ks++) {
            ldsm_x4(qfh[ks], uQh + sw_off(arow, 2 * ks + achs));
            ldsm_x4(qfl[ks], uQl + sw_off(arow, 2 * ks + achs));
        }
    }

    // o[0..7] = output dims; o[8] = softmax normalizer (ones-column block)
    float o[9][4];
#pragma unroll
    for (int nb = 0; nb < 9; nb++)
#pragma unroll
        for (int c = 0; c < 4; c++) o[nb][c] = 0.0f;
    float m0r = -INFINITY, m1r = -INFINITY;

    const uint32_t ones2[2] = { ONES_F16X2, ONES_F16X2 };

    const int b_row = (lane & 7) + ((lane >> 4) << 3);
    const int b_chs = (lane >> 3) & 1;
    const int v_row = (lane & 7) + (((lane >> 3) & 1) << 3);
    const int v_chs = (lane >> 4);

    for (int kb = 0; kb <= qb; kb++) {
        const int st = kb % 3;
        if (kb < qb) CP_WAIT1(); else CP_WAIT0();
        __syncthreads();

        // prefetch kb+2 into the stage last read at kb-1 (ordered by barrier)
        if (kb + 2 <= qb) {
            load_kv((kb + 2) % 3, kb + 2);
            CP_COMMIT();
        }

        const uint32_t uKh = uKV + st * ATT_STAGE;
        const uint32_t uKl = uKh + 16384;
        const uint32_t uVh = uKh + 32768;

        // ---- S = Q @ K^T (log2 domain; 16 n-blocks of 8 keys) ----
        float s[16][4];
#pragma unroll
        for (int nb = 0; nb < 16; nb++)
#pragma unroll
            for (int c = 0; c < 4; c++) s[nb][c] = 0.0f;

#pragma unroll
        for (int nb = 0; nb < 16; nb += 2) {
#pragma unroll
            for (int ks = 0; ks < 4; ks++) {
                uint32_t kh4[4], kl4[4];
                const uint32_t so = sw_off(nb * 8 + b_row, 2 * ks + b_chs);
                ldsm_x4(kh4, uKh + so);
                ldsm_x4(kl4, uKl + so);
                mma_bf16(s[nb], qfh[ks], kh4);
                mma_bf16(s[nb], qfl[ks], kh4);
                mma_bf16(s[nb], qfh[ks], kl4);
                mma_bf16(s[nb + 1], qfh[ks], kh4 + 2);
                mma_bf16(s[nb + 1], qfl[ks], kh4 + 2);
                mma_bf16(s[nb + 1], qfh[ks], kl4 + 2);
            }
        }

        // ---- causal mask on the diagonal block ----
        if (kb == qb) {
            const int ra = r0 + g, rb = r0 + g + 8;
#pragma unroll
            for (int nb = 0; nb < 16; nb++) {
                const int cb = nb * 8 + t * 2;
                if (cb > ra)     s[nb][0] = -1e30f;
                if (cb + 1 > ra) s[nb][1] = -1e30f;
                if (cb > rb)     s[nb][2] = -1e30f;
                if (cb + 1 > rb) s[nb][3] = -1e30f;
            }
        }

        // ---- online softmax in exp2 domain (rows g / g+8) ----
        float mx0 = -INFINITY, mx1 = -INFINITY;
#pragma unroll
        for (int nb = 0; nb < 16; nb++) {
            mx0 = fmaxf(mx0, fmaxf(s[nb][0], s[nb][1]));
            mx1 = fmaxf(mx1, fmaxf(s[nb][2], s[nb][3]));
        }
        mx0 = fmaxf(mx0, __shfl_xor_sync(0xffffffffu, mx0, 1));
        mx0 = fmaxf(mx0, __shfl_xor_sync(0xffffffffu, mx0, 2));
        mx1 = fmaxf(mx1, __shfl_xor_sync(0xffffffffu, mx1, 1));
        mx1 = fmaxf(mx1, __shfl_xor_sync(0xffffffffu, mx1, 2));
        const float mn0 = fmaxf(m0r, mx0);
        const float mn1 = fmaxf(m1r, mx1);
        const float c0 = ex2f(m0r - mn0);
        const float c1 = ex2f(m1r - mn1);
        m0r = mn0; m1r = mn1;
#pragma unroll
        for (int nb = 0; nb < 16; nb++) {
            s[nb][0] = ex2f(s[nb][0] - mn0);
            s[nb][1] = ex2f(s[nb][1] - mn0);
            s[nb][2] = ex2f(s[nb][2] - mn1);
            s[nb][3] = ex2f(s[nb][3] - mn1);
        }
        // rescale O and the normalizer block together
#pragma unroll
        for (int nb = 0; nb < 9; nb++) {
            o[nb][0] *= c0; o[nb][1] *= c0;
            o[nb][2] *= c1; o[nb][3] *= c1;
        }

        // ---- O += P @ V : P fp16, V fp16 (1 term) + ones column ----
#pragma unroll
        for (int kk = 0; kk < 8; kk++) {
            uint32_t pf[4];
            pf[0] = packhf(s[2 * kk][0], s[2 * kk][1]);
            pf[1] = packhf(s[2 * kk][2], s[2 * kk][3]);
            pf[2] = packhf(s[2 * kk + 1][0], s[2 * kk + 1][1]);
            pf[3] = packhf(s[2 * kk + 1][2], s[2 * kk + 1][3]);
#pragma unroll
            for (int nb = 0; nb < 8; nb += 2) {
                uint32_t vh4[4];
                const uint32_t so = sw_off(kk * 16 + v_row, nb + v_chs);
                ldsm_x4_t(vh4, uVh + so);
                mma_f16(o[nb], pf, vh4);
                mma_f16(o[nb + 1], pf, vh4 + 2);
            }
            mma_f16(o[8], pf, ones2);   // row sums of P -> normalizer
        }
    }

    // ---- normalize and write y (bf16 hi/lo split) ----
    const float inv0 = 1.0f / o[8][0];
    const float inv1 = 1.0f / o[8][2];
    const int row0 = qb * 128 + r0 + g;
    const int row1 = row0 + 8;
#pragma unroll
    for (int nb = 0; nb < 8; nb++) {
        const int col = h * HDIM + nb * 8 + t * 2;
        float a0 = o[nb][0] * inv0, a1 = o[nb][1] * inv0;
        float b0 = o[nb][2] * inv1, b1 = o[nb][3] * inv1;
        uint32_t h0 = packbf(a0, a1);
        uint32_t l0 = packbf(a0 - lo_f(h0), a1 - hi_f(h0));
        uint32_t h1 = packbf(b0, b1);
        uint32_t l1 = packbf(b0 - lo_f(h1), b1 - hi_f(h1));
        *reinterpret_cast<uint32_t*>(yh + (size_t)row0 * C_DIM + col) = h0;
        *reinterpret_cast<uint32_t*>(yl + (size_t)row0 * C_DIM + col) = l0;
        *reinterpret_cast<uint32_t*>(yh + (size_t)row1 * C_DIM + col) = h1;
        *reinterpret_cast<uint32_t*>(yl + (size_t)row1 * C_DIM + col) = l1;
    }
}

// ---------------------------------------------------------------------------
// Launch
// ---------------------------------------------------------------------------
extern "C" void kernel_launch(void* const* d_in, const int* in_sizes, int n_in,
                              void* d_out, int out_size)
{
    (void)in_sizes; (void)n_in; (void)out_size;
    const float* x      = (const float*)d_in[0];
    const float* W_qkv  = (const float*)d_in[2];
    const float* b_qkv  = (const float*)d_in[3];
    const float* W_proj = (const float*)d_in[4];
    const float* b_proj = (const float*)d_in[5];
    float* out = (float*)d_out;

    __nv_bfloat16 *xh, *xl, *qkvh, *qkvl, *yh, *yl, *wqh, *wql, *wph, *wpl;
    cudaGetSymbolAddress((void**)&xh, g_xh);
    cudaGetSymbolAddress((void**)&xl, g_xl);
    cudaGetSymbolAddress((void**)&qkvh, g_qkvh);
    cudaGetSymbolAddress((void**)&qkvl, g_qkvl);
    cudaGetSymbolAddress((void**)&yh, g_yh);
    cudaGetSymbolAddress((void**)&yl, g_yl);
    cudaGetSymbolAddress((void**)&wqh, g_wqh);
    cudaGetSymbolAddress((void**)&wql, g_wql);
    cudaGetSymbolAddress((void**)&wph, g_wph);
    cudaGetSymbolAddress((void**)&wpl, g_wpl);

    cudaFuncSetAttribute(gemm_mma,
                         cudaFuncAttributeMaxDynamicSharedMemorySize, GEMM_SMEM);
    cudaFuncSetAttribute(attn_mma,
                         cudaFuncAttributeMaxDynamicSharedMemorySize, ATT_SMEM);

    // 0) prep: weight transpose+split, input split
    transpose_split<<<dim3(QKV3 / 32, C_DIM / 32), 256>>>(
        W_qkv, wqh, wql, C_DIM, QKV3);
    transpose_split<<<dim3(C_DIM / 32, C_DIM / 32), 256>>>(
        W_proj, wph, wpl, C_DIM, C_DIM);
    split_f32<<<(T_SEQ * C_DIM / 4 + 255) / 256, 256>>>(
        x, xh, xl, T_SEQ * C_DIM / 4);

    // 1) qkv = x @ W_qkv + b_qkv; Q -> log2 domain bf16, K bf16, V fp16
    gemm_mma<<<dim3(QKV3 / 256, T_SEQ / 128), 256, GEMM_SMEM>>>(
        xh, xl, wqh, wql, b_qkv, nullptr, qkvh, qkvl, T_SEQ, QKV3, C_DIM, 1);

    // 2) y = causal_attention(qkv) -> bf16 hi/lo
    attn_mma<<<dim3(T_SEQ / 128, NHEAD), 256, ATT_SMEM>>>(qkvh, qkvl, yh, yl);

    // 3) out = y @ W_proj + b_proj (fp32)
    gemm_mma<<<dim3(C_DIM / 256, T_SEQ / 128), 256, GEMM_SMEM>>>(
        yh, yl, wph, wpl, b_proj, out, nullptr, nullptr, T_SEQ, C_DIM, C_DIM, 0);
}

// round 13
// speedup vs baseline: 1.1584x; 1.0048x over previous
#include <cuda_runtime.h>
#include <cuda_bf16.h>
#include <cuda_fp16.h>
#include <math.h>
#include <stdint.h>

// Problem constants
#define T_SEQ 4096
#define C_DIM 768
#define NHEAD 12
#define HDIM  64
#define QKV3  (3 * C_DIM)

// ---------------------------------------------------------------------------
// Scratch (allocation-guard-safe device globals) — bf16 hi/lo split pairs
// (V region of qkv holds fp16; only the hi plane is used for V)
// ---------------------------------------------------------------------------
__device__ __nv_bfloat16 g_xh[(size_t)T_SEQ * C_DIM];
__device__ __nv_bfloat16 g_xl[(size_t)T_SEQ * C_DIM];
__device__ __nv_bfloat16 g_qkvh[(size_t)T_SEQ * QKV3];
__device__ __nv_bfloat16 g_qkvl[(size_t)T_SEQ * QKV3];
__device__ __nv_bfloat16 g_yh[(size_t)T_SEQ * C_DIM];
__device__ __nv_bfloat16 g_yl[(size_t)T_SEQ * C_DIM];
__device__ __nv_bfloat16 g_wqh[(size_t)QKV3 * C_DIM];   // W_qkv^T [3C][C]
__device__ __nv_bfloat16 g_wql[(size_t)QKV3 * C_DIM];
__device__ __nv_bfloat16 g_wph[(size_t)C_DIM * C_DIM];  // W_proj^T [C][C]
__device__ __nv_bfloat16 g_wpl[(size_t)C_DIM * C_DIM];

// ---------------------------------------------------------------------------
// MMA / ldmatrix / cp.async helpers (sm_80+ PTX; assembles on plain sm_103)
// ---------------------------------------------------------------------------
__device__ __forceinline__ uint32_t smem_u32(const void* p) {
    uint32_t a;
    asm("{ .reg .u64 t; cvta.to.shared.u64 t, %1; cvt.u32.u64 %0, t; }"
        : "=r"(a) : "l"(p));
    return a;
}
__device__ __forceinline__ void mma_bf16(float* c, const uint32_t* a,
                                         const uint32_t* b) {
    asm volatile(
        "mma.sync.aligned.m16n8k16.row.col.f32.bf16.bf16.f32 "
        "{%0,%1,%2,%3}, {%4,%5,%6,%7}, {%8,%9}, {%0,%1,%2,%3};"
        : "+f"(c[0]), "+f"(c[1]), "+f"(c[2]), "+f"(c[3])
        : "r"(a[0]), "r"(a[1]), "r"(a[2]), "r"(a[3]), "r"(b[0]), "r"(b[1]));
}
__device__ __forceinline__ void mma_f16(float* c, const uint32_t* a,
                                        const uint32_t* b) {
    asm volatile(
        "mma.sync.aligned.m16n8k16.row.col.f32.f16.f16.f32 "
        "{%0,%1,%2,%3}, {%4,%5,%6,%7}, {%8,%9}, {%0,%1,%2,%3};"
        : "+f"(c[0]), "+f"(c[1]), "+f"(c[2]), "+f"(c[3])
        : "r"(a[0]), "r"(a[1]), "r"(a[2]), "r"(a[3]), "r"(b[0]), "r"(b[1]));
}
__device__ __forceinline__ void ldsm_x4(uint32_t* r, uint32_t a) {
    asm volatile("ldmatrix.sync.aligned.m8n8.x4.shared.b16 {%0,%1,%2,%3}, [%4];"
                 : "=r"(r[0]), "=r"(r[1]), "=r"(r[2]), "=r"(r[3]) : "r"(a));
}
__device__ __forceinline__ void ldsm_x4_t(uint32_t* r, uint32_t a) {
    asm volatile("ldmatrix.sync.aligned.m8n8.x4.trans.shared.b16 {%0,%1,%2,%3}, [%4];"
                 : "=r"(r[0]), "=r"(r[1]), "=r"(r[2]), "=r"(r[3]) : "r"(a));
}
__device__ __forceinline__ void cp16(uint32_t dst, const void* src) {
    asm volatile("cp.async.cg.shared.global [%0], [%1], 16;"
                 :: "r"(dst), "l"(src));
}
#define CP_COMMIT() asm volatile("cp.async.commit_group;" ::: "memory")
#define CP_WAIT1()  asm volatile("cp.async.wait_group 1;" ::: "memory")
#define CP_WAIT0()  asm volatile("cp.async.wait_group 0;" ::: "memory")

// pack two f32 -> bf16x2 / f16x2 (first arg -> low half)
__device__ __forceinline__ uint32_t packbf(float lo, float hi) {
    uint32_t d;
    asm("cvt.rn.bf16x2.f32 %0, %1, %2;" : "=r"(d) : "f"(hi), "f"(lo));
    return d;
}
__device__ __forceinline__ uint32_t packhf(float lo, float hi) {
    uint32_t d;
    asm("cvt.rn.f16x2.f32 %0, %1, %2;" : "=r"(d) : "f"(hi), "f"(lo));
    return d;
}
__device__ __forceinline__ float lo_f(uint32_t u) { return __uint_as_float(u << 16); }
__device__ __forceinline__ float hi_f(uint32_t u) { return __uint_as_float(u & 0xffff0000u); }
__device__ __forceinline__ float ex2f(float x) {
    float y;
    asm("ex2.approx.f32 %0, %1;" : "=f"(y) : "f"(x));
    return y;
}

// byte offset into a [rows][64]-bf16 tile with chunk-XOR swizzle (16B chunks)
__device__ __forceinline__ uint32_t sw_off(int row, int chunk) {
    return (uint32_t)((row << 7) + (((chunk ^ row) & 7) << 4) + ((chunk & ~7) << 4));
}

// ---------------------------------------------------------------------------
// Prep: fp32 -> bf16 hi/lo split (float4 granularity)
// ---------------------------------------------------------------------------
__global__ __launch_bounds__(256) void split_f32(
    const float* __restrict__ X, __nv_bfloat16* __restrict__ Xh,
    __nv_bfloat16* __restrict__ Xl, int n4)
{
    int i = blockIdx.x * 256 + threadIdx.x;
    if (i >= n4) return;
    float4 x = reinterpret_cast<const float4*>(X)[i];
    uint32_t h0 = packbf(x.x, x.y);
    uint32_t h1 = packbf(x.z, x.w);
    uint32_t l0 = packbf(x.x - lo_f(h0), x.y - hi_f(h0));
    uint32_t l1 = packbf(x.z - lo_f(h1), x.w - hi_f(h1));
    reinterpret_cast<uint2*>(Xh)[i] = make_uint2(h0, h1);
    reinterpret_cast<uint2*>(Xl)[i] = make_uint2(l0, l1);
}

// ---------------------------------------------------------------------------
// Prep: W[K][N] -> Wt hi/lo [N][K]
// ---------------------------------------------------------------------------
__global__ __launch_bounds__(256) void transpose_split(
    const float* __restrict__ W, __nv_bfloat16* __restrict__ Th,
    __nv_bfloat16* __restrict__ Tl, int K, int N)
{
    __shared__ float tile[32][33];
    const int tx = threadIdx.x & 31;
    const int ty = threadIdx.x >> 5;
    const int n0 = blockIdx.x * 32;
    const int k0 = blockIdx.y * 32;
#pragma unroll
    for (int i = 0; i < 4; i++)
        tile[ty + 8 * i][tx] = W[(size_t)(k0 + ty + 8 * i) * N + n0 + tx];
    __syncthreads();
#pragma unroll
    for (int i = 0; i < 4; i++) {
        const float v = tile[tx][ty + 8 * i];
        const float h = __bfloat162float(__float2bfloat16_rn(v));
        const size_t o = (size_t)(n0 + ty + 8 * i) * K + k0 + tx;
        Th[o] = __float2bfloat16_rn(h);
        Tl[o] = __float2bfloat16_rn(v - h);
    }
}

// ---------------------------------------------------------------------------
// Split-bf16 HMMA GEMM, CTA 128x256, warp tile 64x64 (2m x 4n warps),
// k-chunk 64, 2-stage cp.async pipeline (96KB/stage, 1 barrier/iter).
// C[M,N] = (Ah+Al)[M,K] @ ((Bh+Bl)[N,K])^T + bias
// mode=1 (QKV): bf16 hi/lo out; Q cols scaled by 0.125*log2(e);
//               V cols (>=2C) written as fp16 (hi plane used by attention).
// mode=0: fp32 out.  Requires N % 256 == 0.
// ---------------------------------------------------------------------------
#define GEMM_STAGE 98304
#define GEMM_SMEM (2 * GEMM_STAGE)
#define QSCALE 0.18033688011112042f   // 0.125 * log2(e)

__global__ __launch_bounds__(256) void gemm_mma(
    const __nv_bfloat16* __restrict__ Ah, const __nv_bfloat16* __restrict__ Al,
    const __nv_bfloat16* __restrict__ Bh, const __nv_bfloat16* __restrict__ Bl,
    const float* __restrict__ bias, float* __restrict__ Cf,
    __nv_bfloat16* __restrict__ Ch, __nv_bfloat16* __restrict__ Cl,
    int M, int N, int K, int mode)
{
    extern __shared__ char smb[];
    const uint32_t ubase = smem_u32(smb);

    const int tid = threadIdx.x;
    const int w = tid >> 5, lane = tid & 31;
    const int g = lane >> 2, t = lane & 3;
    const int wm = w & 1, wn = w >> 1;       // 2 m-strips x 4 n-strips
    const int by = blockIdx.y, bx = blockIdx.x;

    float acc[4][8][4];                       // mi (16 rows) x nb (8 cols)
#pragma unroll
    for (int mi = 0; mi < 4; mi++)
#pragma unroll
        for (int nb = 0; nb < 8; nb++)
#pragma unroll
            for (int c = 0; c < 4; c++) acc[mi][nb][c] = 0.0f;

    const int a_row = (lane & 15);
    const int a_chs = (lane >> 4);
    const int b_row = (lane & 7) + ((lane >> 4) << 3);
    const int b_chs = (lane >> 3) & 1;

    const int NI = K / 64;

    // stage layout: Ah 0 (16KB) | Al 16K | Bh 32K (32KB) | Bl 64K (32KB)
    auto load_stage = [&](int st, int k0) {
        const uint32_t ub = ubase + st * GEMM_STAGE;
#pragma unroll
        for (int j = 0; j < 4; j++) {         // A: 128 rows x 8 chunks
            const int i = tid + 256 * j;
            const int row = i >> 3, ch = i & 7;
            const size_t ga = (size_t)(by * 128 + row) * K + k0 + ch * 8;
            const uint32_t so = sw_off(row, ch);
            cp16(ub + so, Ah + ga);
            cp16(ub + 16384 + so, Al + ga);
        }
#pragma unroll
        for (int j = 0; j < 8; j++) {         // B: 256 rows x 8 chunks
            const int i = tid + 256 * j;
            const int row = i >> 3, ch = i & 7;
            const size_t gb = (size_t)(bx * 256 + row) * K + k0 + ch * 8;
            const uint32_t so = sw_off(row, ch);
            cp16(ub + 32768 + so, Bh + gb);
            cp16(ub + 65536 + so, Bl + gb);
        }
    };

    load_stage(0, 0);
    CP_COMMIT();

    for (int it = 0; it < NI; it++) {
        const int st = it & 1;
        CP_WAIT0();
        __syncthreads();
        if (it + 1 < NI) {
            load_stage(st ^ 1, (it + 1) * 64);
            CP_COMMIT();
        }

        const uint32_t uAh = ubase + st * GEMM_STAGE;
        const uint32_t uAl = uAh + 16384;
        const uint32_t uBh = uAh + 32768;
        const uint32_t uBl = uAh + 65536;

#pragma unroll
        for (int ks = 0; ks < 4; ks++) {
            uint32_t ah[4][4], al[4][4];
#pragma unroll
            for (int mi = 0; mi < 4; mi++) {
                const uint32_t so = sw_off(wm * 64 + mi * 16 + a_row, 2 * ks + a_chs);
                ldsm_x4(ah[mi], uAh + so);
                ldsm_x4(al[mi], uAl + so);
            }
#pragma unroll
            for (int nb = 0; nb < 8; nb += 2) {
                uint32_t bh4[4], bl4[4];
                const uint32_t so = sw_off(wn * 64 + nb * 8 + b_row, 2 * ks + b_chs);
                ldsm_x4(bh4, uBh + so);
                ldsm_x4(bl4, uBl + so);
#pragma unroll
                for (int mi = 0; mi < 4; mi++) {
                    mma_bf16(acc[mi][nb], ah[mi], bh4);
                    mma_bf16(acc[mi][nb], al[mi], bh4);
                    mma_bf16(acc[mi][nb], ah[mi], bl4);
                    mma_bf16(acc[mi][nb + 1], ah[mi], bh4 + 2);
                    mma_bf16(acc[mi][nb + 1], al[mi], bh4 + 2);
                    mma_bf16(acc[mi][nb + 1], ah[mi], bl4 + 2);
                }
            }
        }
    }

    // Epilogue
    const bool v_region = (mode == 1) && (bx * 256 >= 2 * C_DIM);  // V cols -> fp16
#pragma unroll
    for (int mi = 0; mi < 4; mi++) {
#pragma unroll
        for (int nb = 0; nb < 8; nb++) {
            const int row = by * 128 + wm * 64 + mi * 16 + g;
            const int col = bx * 256 + wn * 64 + nb * 8 + t * 2;
            const float2 bb = *reinterpret_cast<const float2*>(bias + col);
            float v0 = acc[mi][nb][0] + bb.x;
            float v1 = acc[mi][nb][1] + bb.y;
            float v2 = acc[mi][nb][2] + bb.x;
            float v3 = acc[mi][nb][3] + bb.y;
            if (mode) {
                if (v_region) {
                    // V: single fp16 (hi plane only; attention ignores lo)
                    *reinterpret_cast<uint32_t*>(Ch + (size_t)row * N + col) =
                        packhf(v0, v1);
                    *reinterpret_cast<uint32_t*>(Ch + (size_t)(row + 8) * N + col) =
                        packhf(v2, v3);
                } else {
                    const float sc = (col < C_DIM) ? QSCALE : 1.0f;  // Q -> log2 domain
                    v0 *= sc; v1 *= sc; v2 *= sc; v3 *= sc;
                    uint32_t h0 = packbf(v0, v1);
                    uint32_t l0 = packbf(v0 - lo_f(h0), v1 - hi_f(h0));
                    uint32_t h1 = packbf(v2, v3);
                    uint32_t l1 = packbf(v2 - lo_f(h1), v3 - hi_f(h1));
                    *reinterpret_cast<uint32_t*>(Ch + (size_t)row * N + col) = h0;
                    *reinterpret_cast<uint32_t*>(Cl + (size_t)row * N + col) = l0;
                    *reinterpret_cast<uint32_t*>(Ch + (size_t)(row + 8) * N + col) = h1;
                    *reinterpret_cast<uint32_t*>(Cl + (size_t)(row + 8) * N + col) = l1;
                }
            } else {
                *reinterpret_cast<float2*>(Cf + (size_t)row * N + col) =
                    make_float2(v0, v1);
                *reinterpret_cast<float2*>(Cf + (size_t)(row + 8) * N + col) =
                    make_float2(v2, v3);
            }
        }
    }
}

// ---------------------------------------------------------------------------
// Flash attention: S = split-bf16 3-term HMMA; PV = single-fp16 1-term with
// an all-ones constant B-fragment accumulating the softmax normalizer.
// 3-stage cp.async K/V pipeline (48KB/stage), exp2-domain softmax with
// ex2/pack interleaved into the PV MMA stream (per-kk granularity).
// CTA = 128 q-rows x 1 head; 8 warps x 16 q-rows. P in registers (fp16).
// ---------------------------------------------------------------------------
#define ATT_STAGE 49152
#define ATT_SMEM (2 * 16384 + 3 * ATT_STAGE)
#define ONES_F16X2 0x3C003C00u

__global__ __launch_bounds__(256, 1) void attn_mma(
    const __nv_bfloat16* __restrict__ qkvh, const __nv_bfloat16* __restrict__ qkvl,
    __nv_bfloat16* __restrict__ yh, __nv_bfloat16* __restrict__ yl)
{
    extern __shared__ char smb[];
    const uint32_t uQh = smem_u32(smb);
    const uint32_t uQl = uQh + 16384;
    const uint32_t uKV = uQh + 32768;   // stage s: +s*ATT_STAGE (Kh|Kl|Vh)

    const int qb = 31 - (int)blockIdx.x;   // long CTAs first
    const int h = blockIdx.y;
    const int tid = threadIdx.x;
    const int w = tid >> 5, lane = tid & 31;
    const int g = lane >> 2, t = lane & 3;
    const int r0 = w * 16;

    const size_t qoff = (size_t)h * HDIM;
    const size_t koff = C_DIM + (size_t)h * HDIM;
    const size_t voff = 2 * C_DIM + (size_t)h * HDIM;

    auto load_kv = [&](int st, int kb) {
        const uint32_t ub = uKV + st * ATT_STAGE;
#pragma unroll
        for (int j = 0; j < 4; j++) {
            const int i = tid + 256 * j;
            const int row = i >> 3, ch = i & 7;
            const size_t gk = (size_t)(kb * 128 + row) * QKV3 + koff + ch * 8;
            const size_t gv = (size_t)(kb * 128 + row) * QKV3 + voff + ch * 8;
            const uint32_t so = sw_off(row, ch);
            cp16(ub + so, qkvh + gk);
            cp16(ub + 16384 + so, qkvl + gk);
            cp16(ub + 32768 + so, qkvh + gv);
        }
    };

    // Prefetch K/V blocks 0 and 1, then load Q (regular STS) while DMA drains
    load_kv(0, 0);
    CP_COMMIT();
    if (qb >= 1) {
        load_kv(1, 1);
        CP_COMMIT();
    }
#pragma unroll 4
    for (int i = tid; i < 1024; i += 256) {
        const int row = i >> 3, ch = i & 7;
        const size_t gq = (size_t)(qb * 128 + row) * QKV3 + qoff + ch * 8;
        const uint32_t so = sw_off(row, ch);
        *reinterpret_cast<uint4*>(smb + so) =
            *reinterpret_cast<const uint4*>(qkvh + gq);
        *reinterpret_cast<uint4*>(smb + 16384 + so) =
            *reinterpret_cast<const uint4*>(qkvl + gq);
    }
    __syncthreads();

    // Q fragments (registers for the whole kernel); Q already in log2 domain
    uint32_t qfh[4][4], qfl[4][4];
    {
        const int arow = r0 + (lane & 15);
        const int achs = (lane >> 4);
#pragma unroll
        for (int ks = 0; ks < 4; ks++) {
            ldsm_x4(qfh[ks], uQh + sw_off(arow, 2 * ks + achs));
            ldsm_x4(qfl[ks], uQl + sw_off(arow, 2 * ks + achs));
        }
    }

    // o[0..7] = output dims; o[8] = softmax normalizer (ones-column block)
    float o[9][4];
#pragma unroll
    for (int nb = 0; nb < 9; nb++)
#pragma unroll
        for (int c = 0; c < 4; c++) o[nb][c] = 0.0f;
    float m0r = -INFINITY, m1r = -INFINITY;

    const uint32_t ones2[2] = { ONES_F16X2, ONES_F16X2 };

    const int b_row = (lane & 7) + ((lane >> 4) << 3);
    const int b_chs = (lane >> 3) & 1;
    const int v_row = (lane & 7) + (((lane >> 3) & 1) << 3);
    const int v_chs = (lane >> 4);

    for (int kb = 0; kb <= qb; kb++) {
        const int st = kb % 3;
        if (kb < qb) CP_WAIT1(); else CP_WAIT0();
        __syncthreads();

        // prefetch kb+2 into the stage last read at kb-1 (ordered by barrier)
        if (kb + 2 <= qb) {
            load_kv((kb + 2) % 3, kb + 2);
            CP_COMMIT();
        }

        const uint32_t uKh = uKV + st * ATT_STAGE;
        const uint32_t uKl = uKh + 16384;
        const uint32_t uVh = uKh + 32768;

        // ---- S = Q @ K^T (log2 domain; 16 n-blocks of 8 keys) ----
        float s[16][4];
#pragma unroll
        for (int nb = 0; nb < 16; nb++)
#pragma unroll
            for (int c = 0; c < 4; c++) s[nb][c] = 0.0f;

#pragma unroll
        for (int nb = 0; nb < 16; nb += 2) {
#pragma unroll
            for (int ks = 0; ks < 4; ks++) {
                uint32_t kh4[4], kl4[4];
                const uint32_t so = sw_off(nb * 8 + b_row, 2 * ks + b_chs);
                ldsm_x4(kh4, uKh + so);
                ldsm_x4(kl4, uKl + so);
                mma_bf16(s[nb], qfh[ks], kh4);
                mma_bf16(s[nb], qfl[ks], kh4);
                mma_bf16(s[nb], qfh[ks], kl4);
                mma_bf16(s[nb + 1], qfh[ks], kh4 + 2);
                mma_bf16(s[nb + 1], qfl[ks], kh4 + 2);
                mma_bf16(s[nb + 1], qfh[ks], kl4 + 2);
            }
        }

        // ---- causal mask on the diagonal block ----
        if (kb == qb) {
            const int ra = r0 + g, rb = r0 + g + 8;
#pragma unroll
            for (int nb = 0; nb < 16; nb++) {
                const int cb = nb * 8 + t * 2;
                if (cb > ra)     s[nb][0] = -1e30f;
                if (cb + 1 > ra) s[nb][1] = -1e30f;
                if (cb > rb)     s[nb][2] = -1e30f;
                if (cb + 1 > rb) s[nb][3] = -1e30f;
            }
        }

        // ---- online softmax max-phase (rows g / g+8) ----
        float mx0 = -INFINITY, mx1 = -INFINITY;
#pragma unroll
        for (int nb = 0; nb < 16; nb++) {
            mx0 = fmaxf(mx0, fmaxf(s[nb][0], s[nb][1]));
            mx1 = fmaxf(mx1, fmaxf(s[nb][2], s[nb][3]));
        }
        mx0 = fmaxf(mx0, __shfl_xor_sync(0xffffffffu, mx0, 1));
        mx0 = fmaxf(mx0, __shfl_xor_sync(0xffffffffu, mx0, 2));
        mx1 = fmaxf(mx1, __shfl_xor_sync(0xffffffffu, mx1, 1));
        mx1 = fmaxf(mx1, __shfl_xor_sync(0xffffffffu, mx1, 2));
        const float mn0 = fmaxf(m0r, mx0);
        const float mn1 = fmaxf(m1r, mx1);
        const float c0 = ex2f(m0r - mn0);
        const float c1 = ex2f(m1r - mn1);
        m0r = mn0; m1r = mn1;
        // rescale O and the normalizer block
#pragma unroll
        for (int nb = 0; nb < 9; nb++) {
            o[nb][0] *= c0; o[nb][1] *= c0;
            o[nb][2] *= c1; o[nb][3] *= c1;
        }

        // ---- ex2 + pack + PV interleaved per kk chunk ----
        // Each step: 8 MUFU ex2 -> 2 cvt packs x2 -> 5 fp16 MMAs, letting the
        // tensor pipe run while the next chunk's exponentials compute.
#pragma unroll
        for (int kk = 0; kk < 8; kk++) {
            uint32_t pf[4];
            {
                const float e0 = ex2f(s[2 * kk][0] - mn0);
                const float e1 = ex2f(s[2 * kk][1] - mn0);
                const float e2 = ex2f(s[2 * kk][2] - mn1);
                const float e3 = ex2f(s[2 * kk][3] - mn1);
                pf[0] = packhf(e0, e1);
                pf[1] = packhf(e2, e3);
                const float f0 = ex2f(s[2 * kk + 1][0] - mn0);
                const float f1 = ex2f(s[2 * kk + 1][1] - mn0);
                const float f2 = ex2f(s[2 * kk + 1][2] - mn1);
                const float f3 = ex2f(s[2 * kk + 1][3] - mn1);
                pf[2] = packhf(f0, f1);
                pf[3] = packhf(f2, f3);
            }
#pragma unroll
            for (int nb = 0; nb < 8; nb += 2) {
                uint32_t vh4[4];
                const uint32_t so = sw_off(kk * 16 + v_row, nb + v_chs);
                ldsm_x4_t(vh4, uVh + so);
                mma_f16(o[nb], pf, vh4);
                mma_f16(o[nb + 1], pf, vh4 + 2);
            }
            mma_f16(o[8], pf, ones2);   // row sums of P -> normalizer
        }
    }

    // ---- normalize and write y (bf16 hi/lo split) ----
    const float inv0 = 1.0f / o[8][0];
    const float inv1 = 1.0f / o[8][2];
    const int row0 = qb * 128 + r0 + g;
    const int row1 = row0 + 8;
#pragma unroll
    for (int nb = 0; nb < 8; nb++) {
        const int col = h * HDIM + nb * 8 + t * 2;
        float a0 = o[nb][0] * inv0, a1 = o[nb][1] * inv0;
        float b0 = o[nb][2] * inv1, b1 = o[nb][3] * inv1;
        uint32_t h0 = packbf(a0, a1);
        uint32_t l0 = packbf(a0 - lo_f(h0), a1 - hi_f(h0));
        uint32_t h1 = packbf(b0, b1);
        uint32_t l1 = packbf(b0 - lo_f(h1), b1 - hi_f(h1));
        *reinterpret_cast<uint32_t*>(yh + (size_t)row0 * C_DIM + col) = h0;
        *reinterpret_cast<uint32_t*>(yl + (size_t)row0 * C_DIM + col) = l0;
        *reinterpret_cast<uint32_t*>(yh + (size_t)row1 * C_DIM + col) = h1;
        *reinterpret_cast<uint32_t*>(yl + (size_t)row1 * C_DIM + col) = l1;
    }
}

// ---------------------------------------------------------------------------
// Launch
// ---------------------------------------------------------------------------
extern "C" void kernel_launch(void* const* d_in, const int* in_sizes, int n_in,
                              void* d_out, int out_size)
{
    (void)in_sizes; (void)n_in; (void)out_size;
    const float* x      = (const float*)d_in[0];
    const float* W_qkv  = (const float*)d_in[2];
    const float* b_qkv  = (const float*)d_in[3];
    const float* W_proj = (const float*)d_in[4];
    const float* b_proj = (const float*)d_in[5];
    float* out = (float*)d_out;

    __nv_bfloat16 *xh, *xl, *qkvh, *qkvl, *yh, *yl, *wqh, *wql, *wph, *wpl;
    cudaGetSymbolAddress((void**)&xh, g_xh);
    cudaGetSymbolAddress((void**)&xl, g_xl);
    cudaGetSymbolAddress((void**)&qkvh, g_qkvh);
    cudaGetSymbolAddress((void**)&qkvl, g_qkvl);
    cudaGetSymbolAddress((void**)&yh, g_yh);
    cudaGetSymbolAddress((void**)&yl, g_yl);
    cudaGetSymbolAddress((void**)&wqh, g_wqh);
    cudaGetSymbolAddress((void**)&wql, g_wql);
    cudaGetSymbolAddress((void**)&wph, g_wph);
    cudaGetSymbolAddress((void**)&wpl, g_wpl);

    cudaFuncSetAttribute(gemm_mma,
                         cudaFuncAttributeMaxDynamicSharedMemorySize, GEMM_SMEM);
    cudaFuncSetAttribute(attn_mma,
                         cudaFuncAttributeMaxDynamicSharedMemorySize, ATT_SMEM);

    // 0) prep: weight transpose+split, input split
    transpose_split<<<dim3(QKV3 / 32, C_DIM / 32), 256>>>(
        W_qkv, wqh, wql, C_DIM, QKV3);
    transpose_split<<<dim3(C_DIM / 32, C_DIM / 32), 256>>>(
        W_proj, wph, wpl, C_DIM, C_DIM);
    split_f32<<<(T_SEQ * C_DIM / 4 + 255) / 256, 256>>>(
        x, xh, xl, T_SEQ * C_DIM / 4);

    // 1) qkv = x @ W_qkv + b_qkv; Q -> log2 domain bf16, K bf16, V fp16
    gemm_mma<<<dim3(QKV3 / 256, T_SEQ / 128), 256, GEMM_SMEM>>>(
        xh, xl, wqh, wql, b_qkv, nullptr, qkvh, qkvl, T_SEQ, QKV3, C_DIM, 1);

    // 2) y = causal_attention(qkv) -> bf16 hi/lo
    attn_mma<<<dim3(T_SEQ / 128, NHEAD), 256, ATT_SMEM>>>(qkvh, qkvl, yh, yl);

    // 3) out = y @ W_proj + b_proj (fp32)
    gemm_mma<<<dim3(C_DIM / 256, T_SEQ / 128), 256, GEMM_SMEM>>>(
        yh, yl, wph, wpl, b_proj, out, nullptr, nullptr, T_SEQ, C_DIM, C_DIM, 0);
}

// round 14
// speedup vs baseline: 1.1798x; 1.0184x over previous
#include <cuda_runtime.h>
#include <cuda_bf16.h>
#include <cuda_fp16.h>
#include <math.h>
#include <stdint.h>

// Problem constants
#define T_SEQ 4096
#define C_DIM 768
#define NHEAD 12
#define HDIM  64
#define QKV3  (3 * C_DIM)

// ---------------------------------------------------------------------------
// Scratch (allocation-guard-safe device globals) — bf16 hi/lo split pairs
// (V region of qkv holds fp16; only the hi plane is used for V)
// ---------------------------------------------------------------------------
__device__ __nv_bfloat16 g_xh[(size_t)T_SEQ * C_DIM];
__device__ __nv_bfloat16 g_xl[(size_t)T_SEQ * C_DIM];
__device__ __nv_bfloat16 g_qkvh[(size_t)T_SEQ * QKV3];
__device__ __nv_bfloat16 g_qkvl[(size_t)T_SEQ * QKV3];
__device__ __nv_bfloat16 g_yh[(size_t)T_SEQ * C_DIM];
__device__ __nv_bfloat16 g_yl[(size_t)T_SEQ * C_DIM];
__device__ __nv_bfloat16 g_wqh[(size_t)QKV3 * C_DIM];   // W_qkv^T [3C][C]
__device__ __nv_bfloat16 g_wql[(size_t)QKV3 * C_DIM];
__device__ __nv_bfloat16 g_wph[(size_t)C_DIM * C_DIM];  // W_proj^T [C][C]
__device__ __nv_bfloat16 g_wpl[(size_t)C_DIM * C_DIM];

// ---------------------------------------------------------------------------
// MMA / ldmatrix / cp.async helpers (sm_80+ PTX; assembles on plain sm_103)
// ---------------------------------------------------------------------------
__device__ __forceinline__ uint32_t smem_u32(const void* p) {
    uint32_t a;
    asm("{ .reg .u64 t; cvta.to.shared.u64 t, %1; cvt.u32.u64 %0, t; }"
        : "=r"(a) : "l"(p));
    return a;
}
__device__ __forceinline__ void mma_bf16(float* c, const uint32_t* a,
                                         const uint32_t* b) {
    asm volatile(
        "mma.sync.aligned.m16n8k16.row.col.f32.bf16.bf16.f32 "
        "{%0,%1,%2,%3}, {%4,%5,%6,%7}, {%8,%9}, {%0,%1,%2,%3};"
        : "+f"(c[0]), "+f"(c[1]), "+f"(c[2]), "+f"(c[3])
        : "r"(a[0]), "r"(a[1]), "r"(a[2]), "r"(a[3]), "r"(b[0]), "r"(b[1]));
}
__device__ __forceinline__ void mma_f16(float* c, const uint32_t* a,
                                        const uint32_t* b) {
    asm volatile(
        "mma.sync.aligned.m16n8k16.row.col.f32.f16.f16.f32 "
        "{%0,%1,%2,%3}, {%4,%5,%6,%7}, {%8,%9}, {%0,%1,%2,%3};"
        : "+f"(c[0]), "+f"(c[1]), "+f"(c[2]), "+f"(c[3])
        : "r"(a[0]), "r"(a[1]), "r"(a[2]), "r"(a[3]), "r"(b[0]), "r"(b[1]));
}
__device__ __forceinline__ void ldsm_x4(uint32_t* r, uint32_t a) {
    asm volatile("ldmatrix.sync.aligned.m8n8.x4.shared.b16 {%0,%1,%2,%3}, [%4];"
                 : "=r"(r[0]), "=r"(r[1]), "=r"(r[2]), "=r"(r[3]) : "r"(a));
}
__device__ __forceinline__ void ldsm_x4_t(uint32_t* r, uint32_t a) {
    asm volatile("ldmatrix.sync.aligned.m8n8.x4.trans.shared.b16 {%0,%1,%2,%3}, [%4];"
                 : "=r"(r[0]), "=r"(r[1]), "=r"(r[2]), "=r"(r[3]) : "r"(a));
}
__device__ __forceinline__ void cp16(uint32_t dst, const void* src) {
    asm volatile("cp.async.cg.shared.global [%0], [%1], 16;"
                 :: "r"(dst), "l"(src));
}
#define CP_COMMIT() asm volatile("cp.async.commit_group;" ::: "memory")
#define CP_WAIT1()  asm volatile("cp.async.wait_group 1;" ::: "memory")
#define CP_WAIT0()  asm volatile("cp.async.wait_group 0;" ::: "memory")

// pack two f32 -> bf16x2 / f16x2 (first arg -> low half)
__device__ __forceinline__ uint32_t packbf(float lo, float hi) {
    uint32_t d;
    asm("cvt.rn.bf16x2.f32 %0, %1, %2;" : "=r"(d) : "f"(hi), "f"(lo));
    return d;
}
__device__ __forceinline__ uint32_t packhf(float lo, float hi) {
    uint32_t d;
    asm("cvt.rn.f16x2.f32 %0, %1, %2;" : "=r"(d) : "f"(hi), "f"(lo));
    return d;
}
__device__ __forceinline__ float lo_f(uint32_t u) { return __uint_as_float(u << 16); }
__device__ __forceinline__ float hi_f(uint32_t u) { return __uint_as_float(u & 0xffff0000u); }
__device__ __forceinline__ float ex2f(float x) {
    float y;
    asm("ex2.approx.f32 %0, %1;" : "=f"(y) : "f"(x));
    return y;
}

// byte offset into a [rows][64]-bf16 tile with chunk-XOR swizzle (16B chunks)
__device__ __forceinline__ uint32_t sw_off(int row, int chunk) {
    return (uint32_t)((row << 7) + (((chunk ^ row) & 7) << 4) + ((chunk & ~7) << 4));
}

// ---------------------------------------------------------------------------
// Prep: fp32 -> bf16 hi/lo split (float4 granularity)
// ---------------------------------------------------------------------------
__global__ __launch_bounds__(256) void split_f32(
    const float* __restrict__ X, __nv_bfloat16* __restrict__ Xh,
    __nv_bfloat16* __restrict__ Xl, int n4)
{
    int i = blockIdx.x * 256 + threadIdx.x;
    if (i >= n4) return;
    float4 x = reinterpret_cast<const float4*>(X)[i];
    uint32_t h0 = packbf(x.x, x.y);
    uint32_t h1 = packbf(x.z, x.w);
    uint32_t l0 = packbf(x.x - lo_f(h0), x.y - hi_f(h0));
    uint32_t l1 = packbf(x.z - lo_f(h1), x.w - hi_f(h1));
    reinterpret_cast<uint2*>(Xh)[i] = make_uint2(h0, h1);
    reinterpret_cast<uint2*>(Xl)[i] = make_uint2(l0, l1);
}

// ---------------------------------------------------------------------------
// Prep: W[K][N] -> Wt hi/lo [N][K]
// ---------------------------------------------------------------------------
__global__ __launch_bounds__(256) void transpose_split(
    const float* __restrict__ W, __nv_bfloat16* __restrict__ Th,
    __nv_bfloat16* __restrict__ Tl, int K, int N)
{
    __shared__ float tile[32][33];
    const int tx = threadIdx.x & 31;
    const int ty = threadIdx.x >> 5;
    const int n0 = blockIdx.x * 32;
    const int k0 = blockIdx.y * 32;
#pragma unroll
    for (int i = 0; i < 4; i++)
        tile[ty + 8 * i][tx] = W[(size_t)(k0 + ty + 8 * i) * N + n0 + tx];
    __syncthreads();
#pragma unroll
    for (int i = 0; i < 4; i++) {
        const float v = tile[tx][ty + 8 * i];
        const float h = __bfloat162float(__float2bfloat16_rn(v));
        const size_t o = (size_t)(n0 + ty + 8 * i) * K + k0 + tx;
        Th[o] = __float2bfloat16_rn(h);
        Tl[o] = __float2bfloat16_rn(v - h);
    }
}

// ---------------------------------------------------------------------------
// Split-bf16 HMMA GEMM, CTA 128x256, warp tile 64x64 (2m x 4n warps),
// k-chunk 64, 2-stage cp.async pipeline (96KB/stage, 1 barrier/iter).
// C[M,N] = (Ah+Al)[M,K] @ ((Bh+Bl)[N,K])^T + bias
// mode=1 (QKV): bf16 hi/lo out; Q cols scaled by 0.125*log2(e);
//               V cols (>=2C) written as fp16 (hi plane used by attention).
// mode=0: fp32 out.  Requires N % 256 == 0.
// ---------------------------------------------------------------------------
#define GEMM_STAGE 98304
#define GEMM_SMEM (2 * GEMM_STAGE)
#define QSCALE 0.18033688011112042f   // 0.125 * log2(e)

__global__ __launch_bounds__(256) void gemm_mma(
    const __nv_bfloat16* __restrict__ Ah, const __nv_bfloat16* __restrict__ Al,
    const __nv_bfloat16* __restrict__ Bh, const __nv_bfloat16* __restrict__ Bl,
    const float* __restrict__ bias, float* __restrict__ Cf,
    __nv_bfloat16* __restrict__ Ch, __nv_bfloat16* __restrict__ Cl,
    int M, int N, int K, int mode)
{
    extern __shared__ char smb[];
    const uint32_t ubase = smem_u32(smb);

    const int tid = threadIdx.x;
    const int w = tid >> 5, lane = tid & 31;
    const int g = lane >> 2, t = lane & 3;
    const int wm = w & 1, wn = w >> 1;       // 2 m-strips x 4 n-strips
    const int by = blockIdx.y, bx = blockIdx.x;

    float acc[4][8][4];                       // mi (16 rows) x nb (8 cols)
#pragma unroll
    for (int mi = 0; mi < 4; mi++)
#pragma unroll
        for (int nb = 0; nb < 8; nb++)
#pragma unroll
            for (int c = 0; c < 4; c++) acc[mi][nb][c] = 0.0f;

    const int a_row = (lane & 15);
    const int a_chs = (lane >> 4);
    const int b_row = (lane & 7) + ((lane >> 4) << 3);
    const int b_chs = (lane >> 3) & 1;

    const int NI = K / 64;

    // stage layout: Ah 0 (16KB) | Al 16K | Bh 32K (32KB) | Bl 64K (32KB)
    auto load_stage = [&](int st, int k0) {
        const uint32_t ub = ubase + st * GEMM_STAGE;
#pragma unroll
        for (int j = 0; j < 4; j++) {         // A: 128 rows x 8 chunks
            const int i = tid + 256 * j;
            const int row = i >> 3, ch = i & 7;
            const size_t ga = (size_t)(by * 128 + row) * K + k0 + ch * 8;
            const uint32_t so = sw_off(row, ch);
            cp16(ub + so, Ah + ga);
            cp16(ub + 16384 + so, Al + ga);
        }
#pragma unroll
        for (int j = 0; j < 8; j++) {         // B: 256 rows x 8 chunks
            const int i = tid + 256 * j;
            const int row = i >> 3, ch = i & 7;
            const size_t gb = (size_t)(bx * 256 + row) * K + k0 + ch * 8;
            const uint32_t so = sw_off(row, ch);
            cp16(ub + 32768 + so, Bh + gb);
            cp16(ub + 65536 + so, Bl + gb);
        }
    };

    load_stage(0, 0);
    CP_COMMIT();

    for (int it = 0; it < NI; it++) {
        const int st = it & 1;
        CP_WAIT0();
        __syncthreads();
        if (it + 1 < NI) {
            load_stage(st ^ 1, (it + 1) * 64);
            CP_COMMIT();
        }

        const uint32_t uAh = ubase + st * GEMM_STAGE;
        const uint32_t uAl = uAh + 16384;
        const uint32_t uBh = uAh + 32768;
        const uint32_t uBl = uAh + 65536;

#pragma unroll
        for (int ks = 0; ks < 4; ks++) {
            uint32_t ah[4][4], al[4][4];
#pragma unroll
            for (int mi = 0; mi < 4; mi++) {
                const uint32_t so = sw_off(wm * 64 + mi * 16 + a_row, 2 * ks + a_chs);
                ldsm_x4(ah[mi], uAh + so);
                ldsm_x4(al[mi], uAl + so);
            }
#pragma unroll
            for (int nb = 0; nb < 8; nb += 2) {
                uint32_t bh4[4], bl4[4];
                const uint32_t so = sw_off(wn * 64 + nb * 8 + b_row, 2 * ks + b_chs);
                ldsm_x4(bh4, uBh + so);
                ldsm_x4(bl4, uBl + so);
#pragma unroll
                for (int mi = 0; mi < 4; mi++) {
                    mma_bf16(acc[mi][nb], ah[mi], bh4);
                    mma_bf16(acc[mi][nb], al[mi], bh4);
                    mma_bf16(acc[mi][nb], ah[mi], bl4);
                    mma_bf16(acc[mi][nb + 1], ah[mi], bh4 + 2);
                    mma_bf16(acc[mi][nb + 1], al[mi], bh4 + 2);
                    mma_bf16(acc[mi][nb + 1], ah[mi], bl4 + 2);
                }
            }
        }
    }

    // Epilogue
    const bool v_region = (mode == 1) && (bx * 256 >= 2 * C_DIM);  // V cols -> fp16
#pragma unroll
    for (int mi = 0; mi < 4; mi++) {
#pragma unroll
        for (int nb = 0; nb < 8; nb++) {
            const int row = by * 128 + wm * 64 + mi * 16 + g;
            const int col = bx * 256 + wn * 64 + nb * 8 + t * 2;
            const float2 bb = *reinterpret_cast<const float2*>(bias + col);
            float v0 = acc[mi][nb][0] + bb.x;
            float v1 = acc[mi][nb][1] + bb.y;
            float v2 = acc[mi][nb][2] + bb.x;
            float v3 = acc[mi][nb][3] + bb.y;
            if (mode) {
                if (v_region) {
                    // V: single fp16 (hi plane only; attention ignores lo)
                    *reinterpret_cast<uint32_t*>(Ch + (size_t)row * N + col) =
                        packhf(v0, v1);
                    *reinterpret_cast<uint32_t*>(Ch + (size_t)(row + 8) * N + col) =
                        packhf(v2, v3);
                } else {
                    const float sc = (col < C_DIM) ? QSCALE : 1.0f;  // Q -> log2 domain
                    v0 *= sc; v1 *= sc; v2 *= sc; v3 *= sc;
                    uint32_t h0 = packbf(v0, v1);
                    uint32_t l0 = packbf(v0 - lo_f(h0), v1 - hi_f(h0));
                    uint32_t h1 = packbf(v2, v3);
                    uint32_t l1 = packbf(v2 - lo_f(h1), v3 - hi_f(h1));
                    *reinterpret_cast<uint32_t*>(Ch + (size_t)row * N + col) = h0;
                    *reinterpret_cast<uint32_t*>(Cl + (size_t)row * N + col) = l0;
                    *reinterpret_cast<uint32_t*>(Ch + (size_t)(row + 8) * N + col) = h1;
                    *reinterpret_cast<uint32_t*>(Cl + (size_t)(row + 8) * N + col) = l1;
                }
            } else {
                *reinterpret_cast<float2*>(Cf + (size_t)row * N + col) =
                    make_float2(v0, v1);
                *reinterpret_cast<float2*>(Cf + (size_t)(row + 8) * N + col) =
                    make_float2(v2, v3);
            }
        }
    }
}

// ---------------------------------------------------------------------------
// Flash attention v3: 128-thread CTA (4 warps), q-tile 64 rows, 2 CTAs/SM.
// Two independent CTAs per SM decouple softmax phases so the tensor pipe
// stays fed. S = split-bf16 3-term; PV = fp16 1-term + ones-column
// normalizer. 2-stage cp.async K/V pipeline (48KB/stage), exp2 softmax.
// SMEM: Q 16KB + 2 x 48KB = 112KB -> 2 CTAs/SM.
// ---------------------------------------------------------------------------
#define ATT_STAGE 49152
#define ATT_SMEM (16384 + 2 * ATT_STAGE)
#define ONES_F16X2 0x3C003C00u

__global__ __launch_bounds__(128, 2) void attn_mma(
    const __nv_bfloat16* __restrict__ qkvh, const __nv_bfloat16* __restrict__ qkvl,
    __nv_bfloat16* __restrict__ yh, __nv_bfloat16* __restrict__ yl)
{
    extern __shared__ char smb[];
    const uint32_t uQh = smem_u32(smb);
    const uint32_t uQl = uQh + 8192;
    const uint32_t uKV = uQh + 16384;   // stage s: +s*ATT_STAGE (Kh|Kl|Vh)

    const int qb = 63 - (int)blockIdx.x;   // 64-row q-block, long CTAs first
    const int h = blockIdx.y;
    const int tid = threadIdx.x;
    const int w = tid >> 5, lane = tid & 31;
    const int g = lane >> 2, t = lane & 3;
    const int r0 = w * 16;                 // warp's rows within the 64-row tile

    // number of 128-key blocks needed: keys 0 .. qb*64+63
    const int nkb = (qb * 64 + 63) / 128 + 1;

    const size_t qoff = (size_t)h * HDIM;
    const size_t koff = C_DIM + (size_t)h * HDIM;
    const size_t voff = 2 * C_DIM + (size_t)h * HDIM;

    auto load_kv = [&](int st, int kb) {
        const uint32_t ub = uKV + st * ATT_STAGE;
#pragma unroll
        for (int j = 0; j < 8; j++) {
            const int i = tid + 128 * j;       // 0..1023
            const int row = i >> 3, ch = i & 7;
            const size_t gk = (size_t)(kb * 128 + row) * QKV3 + koff + ch * 8;
            const size_t gv = (size_t)(kb * 128 + row) * QKV3 + voff + ch * 8;
            const uint32_t so = sw_off(row, ch);
            cp16(ub + so, qkvh + gk);
            cp16(ub + 16384 + so, qkvl + gk);
            cp16(ub + 32768 + so, qkvh + gv);
        }
    };

    // Prefetch K/V block 0, then load Q (64 rows) while the DMA drains
    load_kv(0, 0);
    CP_COMMIT();
#pragma unroll 4
    for (int i = tid; i < 512; i += 128) {
        const int row = i >> 3, ch = i & 7;
        const size_t gq = (size_t)(qb * 64 + row) * QKV3 + qoff + ch * 8;
        const uint32_t so = sw_off(row, ch);
        *reinterpret_cast<uint4*>(smb + so) =
            *reinterpret_cast<const uint4*>(qkvh + gq);
        *reinterpret_cast<uint4*>(smb + 8192 + so) =
            *reinterpret_cast<const uint4*>(qkvl + gq);
    }
    __syncthreads();

    // Q fragments (registers for the whole kernel); Q already in log2 domain
    uint32_t qfh[4][4], qfl[4][4];
    {
        const int arow = r0 + (lane & 15);
        const int achs = (lane >> 4);
#pragma unroll
        for (int ks = 0; ks < 4; ks++) {
            ldsm_x4(qfh[ks], uQh + sw_off(arow, 2 * ks + achs));
            ldsm_x4(qfl[ks], uQl + sw_off(arow, 2 * ks + achs));
        }
    }

    // o[0..7] = output dims; o[8] = softmax normalizer (ones-column block)
    float o[9][4];
#pragma unroll
    for (int nb = 0; nb < 9; nb++)
#pragma unroll
        for (int c = 0; c < 4; c++) o[nb][c] = 0.0f;
    float m0r = -INFINITY, m1r = -INFINITY;

    const uint32_t ones2[2] = { ONES_F16X2, ONES_F16X2 };

    const int b_row = (lane & 7) + ((lane >> 4) << 3);
    const int b_chs = (lane >> 3) & 1;
    const int v_row = (lane & 7) + (((lane >> 3) & 1) << 3);
    const int v_chs = (lane >> 4);

    const int rowg0 = qb * 64 + r0 + g;     // global q rows for this thread
    const int rowg1 = rowg0 + 8;

    for (int kb = 0; kb < nkb; kb++) {
        const int st = kb & 1;
        CP_WAIT0();
        __syncthreads();
        if (kb + 1 < nkb) {
            load_kv(st ^ 1, kb + 1);
            CP_COMMIT();
        }

        const uint32_t uKh = uKV + st * ATT_STAGE;
        const uint32_t uKl = uKh + 16384;
        const uint32_t uVh = uKh + 32768;

        // ---- S = Q @ K^T (log2 domain; 16 n-blocks of 8 keys) ----
        float s[16][4];
#pragma unroll
        for (int nb = 0; nb < 16; nb++)
#pragma unroll
            for (int c = 0; c < 4; c++) s[nb][c] = 0.0f;

#pragma unroll
        for (int nb = 0; nb < 16; nb += 2) {
#pragma unroll
            for (int ks = 0; ks < 4; ks++) {
                uint32_t kh4[4], kl4[4];
                const uint32_t so = sw_off(nb * 8 + b_row, 2 * ks + b_chs);
                ldsm_x4(kh4, uKh + so);
                ldsm_x4(kl4, uKl + so);
                mma_bf16(s[nb], qfh[ks], kh4);
                mma_bf16(s[nb], qfl[ks], kh4);
                mma_bf16(s[nb], qfh[ks], kl4);
                mma_bf16(s[nb + 1], qfh[ks], kh4 + 2);
                mma_bf16(s[nb + 1], qfl[ks], kh4 + 2);
                mma_bf16(s[nb + 1], qfh[ks], kl4 + 2);
            }
        }

        // ---- causal mask on the last key block (global indices) ----
        if (kb == nkb - 1) {
#pragma unroll
            for (int nb = 0; nb < 16; nb++) {
                const int keyg = kb * 128 + nb * 8 + t * 2;
                if (keyg > rowg0)     s[nb][0] = -1e30f;
                if (keyg + 1 > rowg0) s[nb][1] = -1e30f;
                if (keyg > rowg1)     s[nb][2] = -1e30f;
                if (keyg + 1 > rowg1) s[nb][3] = -1e30f;
            }
        }

        // ---- online softmax max-phase (rows g / g+8) ----
        float mx0 = -INFINITY, mx1 = -INFINITY;
#pragma unroll
        for (int nb = 0; nb < 16; nb++) {
            mx0 = fmaxf(mx0, fmaxf(s[nb][0], s[nb][1]));
            mx1 = fmaxf(mx1, fmaxf(s[nb][2], s[nb][3]));
        }
        mx0 = fmaxf(mx0, __shfl_xor_sync(0xffffffffu, mx0, 1));
        mx0 = fmaxf(mx0, __shfl_xor_sync(0xffffffffu, mx0, 2));
        mx1 = fmaxf(mx1, __shfl_xor_sync(0xffffffffu, mx1, 1));
        mx1 = fmaxf(mx1, __shfl_xor_sync(0xffffffffu, mx1, 2));
        const float mn0 = fmaxf(m0r, mx0);
        const float mn1 = fmaxf(m1r, mx1);
        const float c0 = ex2f(m0r - mn0);
        const float c1 = ex2f(m1r - mn1);
        m0r = mn0; m1r = mn1;
        // rescale O and the normalizer block
#pragma unroll
        for (int nb = 0; nb < 9; nb++) {
            o[nb][0] *= c0; o[nb][1] *= c0;
            o[nb][2] *= c1; o[nb][3] *= c1;
        }

        // ---- ex2 + pack + PV per kk chunk (P fp16, V fp16, + ones col) ----
#pragma unroll
        for (int kk = 0; kk < 8; kk++) {
            uint32_t pf[4];
            {
                const float e0 = ex2f(s[2 * kk][0] - mn0);
                const float e1 = ex2f(s[2 * kk][1] - mn0);
                const float e2 = ex2f(s[2 * kk][2] - mn1);
                const float e3 = ex2f(s[2 * kk][3] - mn1);
                pf[0] = packhf(e0, e1);
                pf[1] = packhf(e2, e3);
                const float f0 = ex2f(s[2 * kk + 1][0] - mn0);
                const float f1 = ex2f(s[2 * kk + 1][1] - mn0);
                const float f2 = ex2f(s[2 * kk + 1][2] - mn1);
                const float f3 = ex2f(s[2 * kk + 1][3] - mn1);
                pf[2] = packhf(f0, f1);
                pf[3] = packhf(f2, f3);
            }
#pragma unroll
            for (int nb = 0; nb < 8; nb += 2) {
                uint32_t vh4[4];
                const uint32_t so = sw_off(kk * 16 + v_row, nb + v_chs);
                ldsm_x4_t(vh4, uVh + so);
                mma_f16(o[nb], pf, vh4);
                mma_f16(o[nb + 1], pf, vh4 + 2);
            }
            mma_f16(o[8], pf, ones2);   // row sums of P -> normalizer
        }
    }

    // ---- normalize and write y (bf16 hi/lo split) ----
    const float inv0 = 1.0f / o[8][0];
    const float inv1 = 1.0f / o[8][2];
#pragma unroll
    for (int nb = 0; nb < 8; nb++) {
        const int col = h * HDIM + nb * 8 + t * 2;
        float a0 = o[nb][0] * inv0, a1 = o[nb][1] * inv0;
        float b0 = o[nb][2] * inv1, b1 = o[nb][3] * inv1;
        uint32_t h0 = packbf(a0, a1);
        uint32_t l0 = packbf(a0 - lo_f(h0), a1 - hi_f(h0));
        uint32_t h1 = packbf(b0, b1);
        uint32_t l1 = packbf(b0 - lo_f(h1), b1 - hi_f(h1));
        *reinterpret_cast<uint32_t*>(yh + (size_t)rowg0 * C_DIM + col) = h0;
        *reinterpret_cast<uint32_t*>(yl + (size_t)rowg0 * C_DIM + col) = l0;
        *reinterpret_cast<uint32_t*>(yh + (size_t)rowg1 * C_DIM + col) = h1;
        *reinterpret_cast<uint32_t*>(yl + (size_t)rowg1 * C_DIM + col) = l1;
    }
}

// ---------------------------------------------------------------------------
// Launch
// ---------------------------------------------------------------------------
extern "C" void kernel_launch(void* const* d_in, const int* in_sizes, int n_in,
                              void* d_out, int out_size)
{
    (void)in_sizes; (void)n_in; (void)out_size;
    const float* x      = (const float*)d_in[0];
    const float* W_qkv  = (const float*)d_in[2];
    const float* b_qkv  = (const float*)d_in[3];
    const float* W_proj = (const float*)d_in[4];
    const float* b_proj = (const float*)d_in[5];
    float* out = (float*)d_out;

    __nv_bfloat16 *xh, *xl, *qkvh, *qkvl, *yh, *yl, *wqh, *wql, *wph, *wpl;
    cudaGetSymbolAddress((void**)&xh, g_xh);
    cudaGetSymbolAddress((void**)&xl, g_xl);
    cudaGetSymbolAddress((void**)&qkvh, g_qkvh);
    cudaGetSymbolAddress((void**)&qkvl, g_qkvl);
    cudaGetSymbolAddress((void**)&yh, g_yh);
    cudaGetSymbolAddress((void**)&yl, g_yl);
    cudaGetSymbolAddress((void**)&wqh, g_wqh);
    cudaGetSymbolAddress((void**)&wql, g_wql);
    cudaGetSymbolAddress((void**)&wph, g_wph);
    cudaGetSymbolAddress((void**)&wpl, g_wpl);

    cudaFuncSetAttribute(gemm_mma,
                         cudaFuncAttributeMaxDynamicSharedMemorySize, GEMM_SMEM);
    cudaFuncSetAttribute(attn_mma,
                         cudaFuncAttributeMaxDynamicSharedMemorySize, ATT_SMEM);

    // 0) prep: weight transpose+split, input split
    transpose_split<<<dim3(QKV3 / 32, C_DIM / 32), 256>>>(
        W_qkv, wqh, wql, C_DIM, QKV3);
    transpose_split<<<dim3(C_DIM / 32, C_DIM / 32), 256>>>(
        W_proj, wph, wpl, C_DIM, C_DIM);
    split_f32<<<(T_SEQ * C_DIM / 4 + 255) / 256, 256>>>(
        x, xh, xl, T_SEQ * C_DIM / 4);

    // 1) qkv = x @ W_qkv + b_qkv; Q -> log2 domain bf16, K bf16, V fp16
    gemm_mma<<<dim3(QKV3 / 256, T_SEQ / 128), 256, GEMM_SMEM>>>(
        xh, xl, wqh, wql, b_qkv, nullptr, qkvh, qkvl, T_SEQ, QKV3, C_DIM, 1);

    // 2) y = causal_attention(qkv) -> bf16 hi/lo   (64-row q-tiles, 2 CTA/SM)
    attn_mma<<<dim3(T_SEQ / 64, NHEAD), 128, ATT_SMEM>>>(qkvh, qkvl, yh, yl);

    // 3) out = y @ W_proj + b_proj (fp32)
    gemm_mma<<<dim3(C_DIM / 256, T_SEQ / 128), 256, GEMM_SMEM>>>(
        yh, yl, wph, wpl, b_proj, out, nullptr, nullptr, T_SEQ, C_DIM, C_DIM, 0);
}

// round 15
// speedup vs baseline: 1.3245x; 1.1227x over previous
#include <cuda_runtime.h>
#include <cuda_bf16.h>
#include <cuda_fp16.h>
#include <math.h>
#include <stdint.h>

// Problem constants
#define T_SEQ 4096
#define C_DIM 768
#define NHEAD 12
#define HDIM  64
#define QKV3  (3 * C_DIM)

// ---------------------------------------------------------------------------
// Scratch (allocation-guard-safe device globals).
// qkv planes: Q region = fp16 hi/lo (log2-scaled), K/V regions = fp16 single
// (hi plane only). x/y/W planes remain bf16 hi/lo splits for the GEMMs.
// ---------------------------------------------------------------------------
__device__ __nv_bfloat16 g_xh[(size_t)T_SEQ * C_DIM];
__device__ __nv_bfloat16 g_xl[(size_t)T_SEQ * C_DIM];
__device__ __nv_bfloat16 g_qkvh[(size_t)T_SEQ * QKV3];
__device__ __nv_bfloat16 g_qkvl[(size_t)T_SEQ * QKV3];
__device__ __nv_bfloat16 g_yh[(size_t)T_SEQ * C_DIM];
__device__ __nv_bfloat16 g_yl[(size_t)T_SEQ * C_DIM];
__device__ __nv_bfloat16 g_wqh[(size_t)QKV3 * C_DIM];   // W_qkv^T [3C][C]
__device__ __nv_bfloat16 g_wql[(size_t)QKV3 * C_DIM];
__device__ __nv_bfloat16 g_wph[(size_t)C_DIM * C_DIM];  // W_proj^T [C][C]
__device__ __nv_bfloat16 g_wpl[(size_t)C_DIM * C_DIM];

// ---------------------------------------------------------------------------
// MMA / ldmatrix / cp.async helpers (sm_80+ PTX; assembles on plain sm_103)
// ---------------------------------------------------------------------------
__device__ __forceinline__ uint32_t smem_u32(const void* p) {
    uint32_t a;
    asm("{ .reg .u64 t; cvta.to.shared.u64 t, %1; cvt.u32.u64 %0, t; }"
        : "=r"(a) : "l"(p));
    return a;
}
__device__ __forceinline__ void mma_bf16(float* c, const uint32_t* a,
                                         const uint32_t* b) {
    asm volatile(
        "mma.sync.aligned.m16n8k16.row.col.f32.bf16.bf16.f32 "
        "{%0,%1,%2,%3}, {%4,%5,%6,%7}, {%8,%9}, {%0,%1,%2,%3};"
        : "+f"(c[0]), "+f"(c[1]), "+f"(c[2]), "+f"(c[3])
        : "r"(a[0]), "r"(a[1]), "r"(a[2]), "r"(a[3]), "r"(b[0]), "r"(b[1]));
}
__device__ __forceinline__ void mma_f16(float* c, const uint32_t* a,
                                        const uint32_t* b) {
    asm volatile(
        "mma.sync.aligned.m16n8k16.row.col.f32.f16.f16.f32 "
        "{%0,%1,%2,%3}, {%4,%5,%6,%7}, {%8,%9}, {%0,%1,%2,%3};"
        : "+f"(c[0]), "+f"(c[1]), "+f"(c[2]), "+f"(c[3])
        : "r"(a[0]), "r"(a[1]), "r"(a[2]), "r"(a[3]), "r"(b[0]), "r"(b[1]));
}
__device__ __forceinline__ void ldsm_x4(uint32_t* r, uint32_t a) {
    asm volatile("ldmatrix.sync.aligned.m8n8.x4.shared.b16 {%0,%1,%2,%3}, [%4];"
                 : "=r"(r[0]), "=r"(r[1]), "=r"(r[2]), "=r"(r[3]) : "r"(a));
}
__device__ __forceinline__ void ldsm_x4_t(uint32_t* r, uint32_t a) {
    asm volatile("ldmatrix.sync.aligned.m8n8.x4.trans.shared.b16 {%0,%1,%2,%3}, [%4];"
                 : "=r"(r[0]), "=r"(r[1]), "=r"(r[2]), "=r"(r[3]) : "r"(a));
}
__device__ __forceinline__ void cp16(uint32_t dst, const void* src) {
    asm volatile("cp.async.cg.shared.global [%0], [%1], 16;"
                 :: "r"(dst), "l"(src));
}
#define CP_COMMIT() asm volatile("cp.async.commit_group;" ::: "memory")
#define CP_WAIT1()  asm volatile("cp.async.wait_group 1;" ::: "memory")
#define CP_WAIT0()  asm volatile("cp.async.wait_group 0;" ::: "memory")

// pack two f32 -> bf16x2 / f16x2 (first arg -> low half)
__device__ __forceinline__ uint32_t packbf(float lo, float hi) {
    uint32_t d;
    asm("cvt.rn.bf16x2.f32 %0, %1, %2;" : "=r"(d) : "f"(hi), "f"(lo));
    return d;
}
__device__ __forceinline__ uint32_t packhf(float lo, float hi) {
    uint32_t d;
    asm("cvt.rn.f16x2.f32 %0, %1, %2;" : "=r"(d) : "f"(hi), "f"(lo));
    return d;
}
__device__ __forceinline__ float lo_f(uint32_t u) { return __uint_as_float(u << 16); }
__device__ __forceinline__ float hi_f(uint32_t u) { return __uint_as_float(u & 0xffff0000u); }
__device__ __forceinline__ float lo_h(uint32_t u) {
    __half2 h = *reinterpret_cast<__half2*>(&u);
    return __half2float(h.x);
}
__device__ __forceinline__ float hi_h(uint32_t u) {
    __half2 h = *reinterpret_cast<__half2*>(&u);
    return __half2float(h.y);
}
__device__ __forceinline__ float ex2f(float x) {
    float y;
    asm("ex2.approx.f32 %0, %1;" : "=f"(y) : "f"(x));
    return y;
}

// byte offset into a [rows][64]-bf16 tile with chunk-XOR swizzle (16B chunks)
__device__ __forceinline__ uint32_t sw_off(int row, int chunk) {
    return (uint32_t)((row << 7) + (((chunk ^ row) & 7) << 4) + ((chunk & ~7) << 4));
}

// ---------------------------------------------------------------------------
// Prep: fp32 -> bf16 hi/lo split (float4 granularity)
// ---------------------------------------------------------------------------
__global__ __launch_bounds__(256) void split_f32(
    const float* __restrict__ X, __nv_bfloat16* __restrict__ Xh,
    __nv_bfloat16* __restrict__ Xl, int n4)
{
    int i = blockIdx.x * 256 + threadIdx.x;
    if (i >= n4) return;
    float4 x = reinterpret_cast<const float4*>(X)[i];
    uint32_t h0 = packbf(x.x, x.y);
    uint32_t h1 = packbf(x.z, x.w);
    uint32_t l0 = packbf(x.x - lo_f(h0), x.y - hi_f(h0));
    uint32_t l1 = packbf(x.z - lo_f(h1), x.w - hi_f(h1));
    reinterpret_cast<uint2*>(Xh)[i] = make_uint2(h0, h1);
    reinterpret_cast<uint2*>(Xl)[i] = make_uint2(l0, l1);
}

// ---------------------------------------------------------------------------
// Prep: W[K][N] -> Wt hi/lo [N][K]
// ---------------------------------------------------------------------------
__global__ __launch_bounds__(256) void transpose_split(
    const float* __restrict__ W, __nv_bfloat16* __restrict__ Th,
    __nv_bfloat16* __restrict__ Tl, int K, int N)
{
    __shared__ float tile[32][33];
    const int tx = threadIdx.x & 31;
    const int ty = threadIdx.x >> 5;
    const int n0 = blockIdx.x * 32;
    const int k0 = blockIdx.y * 32;
#pragma unroll
    for (int i = 0; i < 4; i++)
        tile[ty + 8 * i][tx] = W[(size_t)(k0 + ty + 8 * i) * N + n0 + tx];
    __syncthreads();
#pragma unroll
    for (int i = 0; i < 4; i++) {
        const float v = tile[tx][ty + 8 * i];
        const float h = __bfloat162float(__float2bfloat16_rn(v));
        const size_t o = (size_t)(n0 + ty + 8 * i) * K + k0 + tx;
        Th[o] = __float2bfloat16_rn(h);
        Tl[o] = __float2bfloat16_rn(v - h);
    }
}

// ---------------------------------------------------------------------------
// Split-bf16 HMMA GEMM, CTA 128x256, warp tile 64x64 (2m x 4n warps),
// k-chunk 64, 2-stage cp.async pipeline (96KB/stage, 1 barrier/iter).
// C[M,N] = (Ah+Al)[M,K] @ ((Bh+Bl)[N,K])^T + bias
// mode=1 (QKV): Q cols (<C) -> fp16 hi/lo scaled by 0.125*log2(e);
//               K/V cols (>=C) -> single fp16 (hi plane only).
// mode=0: fp32 out.  Requires N % 256 == 0.
// ---------------------------------------------------------------------------
#define GEMM_STAGE 98304
#define GEMM_SMEM (2 * GEMM_STAGE)
#define QSCALE 0.18033688011112042f   // 0.125 * log2(e)

__global__ __launch_bounds__(256) void gemm_mma(
    const __nv_bfloat16* __restrict__ Ah, const __nv_bfloat16* __restrict__ Al,
    const __nv_bfloat16* __restrict__ Bh, const __nv_bfloat16* __restrict__ Bl,
    const float* __restrict__ bias, float* __restrict__ Cf,
    __nv_bfloat16* __restrict__ Ch, __nv_bfloat16* __restrict__ Cl,
    int M, int N, int K, int mode)
{
    extern __shared__ char smb[];
    const uint32_t ubase = smem_u32(smb);

    const int tid = threadIdx.x;
    const int w = tid >> 5, lane = tid & 31;
    const int g = lane >> 2, t = lane & 3;
    const int wm = w & 1, wn = w >> 1;       // 2 m-strips x 4 n-strips
    const int by = blockIdx.y, bx = blockIdx.x;

    float acc[4][8][4];                       // mi (16 rows) x nb (8 cols)
#pragma unroll
    for (int mi = 0; mi < 4; mi++)
#pragma unroll
        for (int nb = 0; nb < 8; nb++)
#pragma unroll
            for (int c = 0; c < 4; c++) acc[mi][nb][c] = 0.0f;

    const int a_row = (lane & 15);
    const int a_chs = (lane >> 4);
    const int b_row = (lane & 7) + ((lane >> 4) << 3);
    const int b_chs = (lane >> 3) & 1;

    const int NI = K / 64;

    // stage layout: Ah 0 (16KB) | Al 16K | Bh 32K (32KB) | Bl 64K (32KB)
    auto load_stage = [&](int st, int k0) {
        const uint32_t ub = ubase + st * GEMM_STAGE;
#pragma unroll
        for (int j = 0; j < 4; j++) {         // A: 128 rows x 8 chunks
            const int i = tid + 256 * j;
            const int row = i >> 3, ch = i & 7;
            const size_t ga = (size_t)(by * 128 + row) * K + k0 + ch * 8;
            const uint32_t so = sw_off(row, ch);
            cp16(ub + so, Ah + ga);
            cp16(ub + 16384 + so, Al + ga);
        }
#pragma unroll
        for (int j = 0; j < 8; j++) {         // B: 256 rows x 8 chunks
            const int i = tid + 256 * j;
            const int row = i >> 3, ch = i & 7;
            const size_t gb = (size_t)(bx * 256 + row) * K + k0 + ch * 8;
            const uint32_t so = sw_off(row, ch);
            cp16(ub + 32768 + so, Bh + gb);
            cp16(ub + 65536 + so, Bl + gb);
        }
    };

    load_stage(0, 0);
    CP_COMMIT();

    for (int it = 0; it < NI; it++) {
        const int st = it & 1;
        CP_WAIT0();
        __syncthreads();
        if (it + 1 < NI) {
            load_stage(st ^ 1, (it + 1) * 64);
            CP_COMMIT();
        }

        const uint32_t uAh = ubase + st * GEMM_STAGE;
        const uint32_t uAl = uAh + 16384;
        const uint32_t uBh = uAh + 32768;
        const uint32_t uBl = uAh + 65536;

#pragma unroll
        for (int ks = 0; ks < 4; ks++) {
            uint32_t ah[4][4], al[4][4];
#pragma unroll
            for (int mi = 0; mi < 4; mi++) {
                const uint32_t so = sw_off(wm * 64 + mi * 16 + a_row, 2 * ks + a_chs);
                ldsm_x4(ah[mi], uAh + so);
                ldsm_x4(al[mi], uAl + so);
            }
#pragma unroll
            for (int nb = 0; nb < 8; nb += 2) {
                uint32_t bh4[4], bl4[4];
                const uint32_t so = sw_off(wn * 64 + nb * 8 + b_row, 2 * ks + b_chs);
                ldsm_x4(bh4, uBh + so);
                ldsm_x4(bl4, uBl + so);
#pragma unroll
                for (int mi = 0; mi < 4; mi++) {
                    mma_bf16(acc[mi][nb], ah[mi], bh4);
                    mma_bf16(acc[mi][nb], al[mi], bh4);
                    mma_bf16(acc[mi][nb], ah[mi], bl4);
                    mma_bf16(acc[mi][nb + 1], ah[mi], bh4 + 2);
                    mma_bf16(acc[mi][nb + 1], al[mi], bh4 + 2);
                    mma_bf16(acc[mi][nb + 1], ah[mi], bl4 + 2);
                }
            }
        }
    }

    // Epilogue
    const bool q_region = (mode == 1) && (bx * 256 < C_DIM);   // Q -> fp16 hi/lo
#pragma unroll
    for (int mi = 0; mi < 4; mi++) {
#pragma unroll
        for (int nb = 0; nb < 8; nb++) {
            const int row = by * 128 + wm * 64 + mi * 16 + g;
            const int col = bx * 256 + wn * 64 + nb * 8 + t * 2;
            const float2 bb = *reinterpret_cast<const float2*>(bias + col);
            float v0 = acc[mi][nb][0] + bb.x;
            float v1 = acc[mi][nb][1] + bb.y;
            float v2 = acc[mi][nb][2] + bb.x;
            float v3 = acc[mi][nb][3] + bb.y;
            if (mode) {
                if (q_region) {
                    v0 *= QSCALE; v1 *= QSCALE; v2 *= QSCALE; v3 *= QSCALE;
                    uint32_t h0 = packhf(v0, v1);
                    uint32_t l0 = packhf(v0 - lo_h(h0), v1 - hi_h(h0));
                    uint32_t h1 = packhf(v2, v3);
                    uint32_t l1 = packhf(v2 - lo_h(h1), v3 - hi_h(h1));
                    *reinterpret_cast<uint32_t*>(Ch + (size_t)row * N + col) = h0;
                    *reinterpret_cast<uint32_t*>(Cl + (size_t)row * N + col) = l0;
                    *reinterpret_cast<uint32_t*>(Ch + (size_t)(row + 8) * N + col) = h1;
                    *reinterpret_cast<uint32_t*>(Cl + (size_t)(row + 8) * N + col) = l1;
                } else {
                    // K/V: single fp16 (hi plane only)
                    *reinterpret_cast<uint32_t*>(Ch + (size_t)row * N + col) =
                        packhf(v0, v1);
                    *reinterpret_cast<uint32_t*>(Ch + (size_t)(row + 8) * N + col) =
                        packhf(v2, v3);
                }
            } else {
                *reinterpret_cast<float2*>(Cf + (size_t)row * N + col) =
                    make_float2(v0, v1);
                *reinterpret_cast<float2*>(Cf + (size_t)(row + 8) * N + col) =
                    make_float2(v2, v3);
            }
        }
    }
}

// ---------------------------------------------------------------------------
// Flash attention v4: 128-thread CTA (4 warps), q-tile 64 rows, 2 CTAs/SM.
// All-fp16 operands: Q fp16 hi/lo (2-term S), K fp16 single, V fp16 single
// (1-term PV + ones-column normalizer). 3-stage cp.async K/V pipeline
// (32KB/stage), exp2-domain softmax.
// SMEM: Q 16KB + 3 x 32KB = 112KB -> 2 CTAs/SM.
// ---------------------------------------------------------------------------
#define ATT_STAGE 32768
#define ATT_SMEM (16384 + 3 * ATT_STAGE)
#define ONES_F16X2 0x3C003C00u

__global__ __launch_bounds__(128, 2) void attn_mma(
    const __nv_bfloat16* __restrict__ qkvh, const __nv_bfloat16* __restrict__ qkvl,
    __nv_bfloat16* __restrict__ yh, __nv_bfloat16* __restrict__ yl)
{
    extern __shared__ char smb[];
    const uint32_t uQh = smem_u32(smb);
    const uint32_t uQl = uQh + 8192;
    const uint32_t uKV = uQh + 16384;   // stage s: +s*ATT_STAGE (Kh|Vh)

    const int qb = 63 - (int)blockIdx.x;   // 64-row q-block, long CTAs first
    const int h = blockIdx.y;
    const int tid = threadIdx.x;
    const int w = tid >> 5, lane = tid & 31;
    const int g = lane >> 2, t = lane & 3;
    const int r0 = w * 16;                 // warp's rows within the 64-row tile

    // number of 128-key blocks needed: keys 0 .. qb*64+63
    const int nkb = (qb * 64 + 63) / 128 + 1;

    const size_t qoff = (size_t)h * HDIM;
    const size_t koff = C_DIM + (size_t)h * HDIM;
    const size_t voff = 2 * C_DIM + (size_t)h * HDIM;

    auto load_kv = [&](int st, int kb) {
        const uint32_t ub = uKV + st * ATT_STAGE;
#pragma unroll
        for (int j = 0; j < 8; j++) {
            const int i = tid + 128 * j;       // 0..1023
            const int row = i >> 3, ch = i & 7;
            const size_t gk = (size_t)(kb * 128 + row) * QKV3 + koff + ch * 8;
            const size_t gv = (size_t)(kb * 128 + row) * QKV3 + voff + ch * 8;
            const uint32_t so = sw_off(row, ch);
            cp16(ub + so, qkvh + gk);
            cp16(ub + 16384 + so, qkvh + gv);
        }
    };

    // Prefetch K/V blocks 0,1, then load Q (64 rows) while the DMA drains
    load_kv(0, 0);
    CP_COMMIT();
    if (nkb > 1) {
        load_kv(1, 1);
        CP_COMMIT();
    }
#pragma unroll 4
    for (int i = tid; i < 512; i += 128) {
        const int row = i >> 3, ch = i & 7;
        const size_t gq = (size_t)(qb * 64 + row) * QKV3 + qoff + ch * 8;
        const uint32_t so = sw_off(row, ch);
        *reinterpret_cast<uint4*>(smb + so) =
            *reinterpret_cast<const uint4*>(qkvh + gq);
        *reinterpret_cast<uint4*>(smb + 8192 + so) =
            *reinterpret_cast<const uint4*>(qkvl + gq);
    }
    __syncthreads();

    // Q fragments (fp16 hi/lo, registers for the whole kernel); log2 domain
    uint32_t qfh[4][4], qfl[4][4];
    {
        const int arow = r0 + (lane & 15);
        const int achs = (lane >> 4);
#pragma unroll
        for (int ks = 0; ks < 4; ks++) {
            ldsm_x4(qfh[ks], uQh + sw_off(arow, 2 * ks + achs));
            ldsm_x4(qfl[ks], uQl + sw_off(arow, 2 * ks + achs));
        }
    }

    // o[0..7] = output dims; o[8] = softmax normalizer (ones-column block)
    float o[9][4];
#pragma unroll
    for (int nb = 0; nb < 9; nb++)
#pragma unroll
        for (int c = 0; c < 4; c++) o[nb][c] = 0.0f;
    float m0r = -INFINITY, m1r = -INFINITY;

    const uint32_t ones2[2] = { ONES_F16X2, ONES_F16X2 };

    const int b_row = (lane & 7) + ((lane >> 4) << 3);
    const int b_chs = (lane >> 3) & 1;
    const int v_row = (lane & 7) + (((lane >> 3) & 1) << 3);
    const int v_chs = (lane >> 4);

    const int rowg0 = qb * 64 + r0 + g;     // global q rows for this thread
    const int rowg1 = rowg0 + 8;

    for (int kb = 0; kb < nkb; kb++) {
        const int st = kb % 3;
        if (kb + 1 < nkb) CP_WAIT1(); else CP_WAIT0();
        __syncthreads();

        // prefetch kb+2 into the stage last read at kb-1 (ordered by barrier)
        if (kb + 2 < nkb) {
            load_kv((kb + 2) % 3, kb + 2);
            CP_COMMIT();
        }

        const uint32_t uKh = uKV + st * ATT_STAGE;
        const uint32_t uVh = uKh + 16384;

        // ---- S = Q @ K^T : Qh/Ql fp16 x K fp16 (2-term, log2 domain) ----
        float s[16][4];
#pragma unroll
        for (int nb = 0; nb < 16; nb++)
#pragma unroll
            for (int c = 0; c < 4; c++) s[nb][c] = 0.0f;

#pragma unroll
        for (int nb = 0; nb < 16; nb += 2) {
#pragma unroll
            for (int ks = 0; ks < 4; ks++) {
                uint32_t kh4[4];
                const uint32_t so = sw_off(nb * 8 + b_row, 2 * ks + b_chs);
                ldsm_x4(kh4, uKh + so);
                mma_f16(s[nb], qfh[ks], kh4);
                mma_f16(s[nb], qfl[ks], kh4);
                mma_f16(s[nb + 1], qfh[ks], kh4 + 2);
                mma_f16(s[nb + 1], qfl[ks], kh4 + 2);
            }
        }

        // ---- causal mask on the last key block (global indices) ----
        if (kb == nkb - 1) {
#pragma unroll
            for (int nb = 0; nb < 16; nb++) {
                const int keyg = kb * 128 + nb * 8 + t * 2;
                if (keyg > rowg0)     s[nb][0] = -1e30f;
                if (keyg + 1 > rowg0) s[nb][1] = -1e30f;
                if (keyg > rowg1)     s[nb][2] = -1e30f;
                if (keyg + 1 > rowg1) s[nb][3] = -1e30f;
            }
        }

        // ---- online softmax max-phase (rows g / g+8) ----
        float mx0 = -INFINITY, mx1 = -INFINITY;
#pragma unroll
        for (int nb = 0; nb < 16; nb++) {
            mx0 = fmaxf(mx0, fmaxf(s[nb][0], s[nb][1]));
            mx1 = fmaxf(mx1, fmaxf(s[nb][2], s[nb][3]));
        }
        mx0 = fmaxf(mx0, __shfl_xor_sync(0xffffffffu, mx0, 1));
        mx0 = fmaxf(mx0, __shfl_xor_sync(0xffffffffu, mx0, 2));
        mx1 = fmaxf(mx1, __shfl_xor_sync(0xffffffffu, mx1, 1));
        mx1 = fmaxf(mx1, __shfl_xor_sync(0xffffffffu, mx1, 2));
        const float mn0 = fmaxf(m0r, mx0);
        const float mn1 = fmaxf(m1r, mx1);
        const float c0 = ex2f(m0r - mn0);
        const float c1 = ex2f(m1r - mn1);
        m0r = mn0; m1r = mn1;
        // rescale O and the normalizer block
#pragma unroll
        for (int nb = 0; nb < 9; nb++) {
            o[nb][0] *= c0; o[nb][1] *= c0;
            o[nb][2] *= c1; o[nb][3] *= c1;
        }

        // ---- ex2 + pack + PV per kk chunk (P fp16, V fp16, + ones col) ----
#pragma unroll
        for (int kk = 0; kk < 8; kk++) {
            uint32_t pf[4];
            {
                const float e0 = ex2f(s[2 * kk][0] - mn0);
                const float e1 = ex2f(s[2 * kk][1] - mn0);
                const float e2 = ex2f(s[2 * kk][2] - mn1);
                const float e3 = ex2f(s[2 * kk][3] - mn1);
                pf[0] = packhf(e0, e1);
                pf[1] = packhf(e2, e3);
                const float f0 = ex2f(s[2 * kk + 1][0] - mn0);
                const float f1 = ex2f(s[2 * kk + 1][1] - mn0);
                const float f2 = ex2f(s[2 * kk + 1][2] - mn1);
                const float f3 = ex2f(s[2 * kk + 1][3] - mn1);
                pf[2] = packhf(f0, f1);
                pf[3] = packhf(f2, f3);
            }
#pragma unroll
            for (int nb = 0; nb < 8; nb += 2) {
                uint32_t vh4[4];
                const uint32_t so = sw_off(kk * 16 + v_row, nb + v_chs);
                ldsm_x4_t(vh4, uVh + so);
                mma_f16(o[nb], pf, vh4);
                mma_f16(o[nb + 1], pf, vh4 + 2);
            }
            mma_f16(o[8], pf, ones2);   // row sums of P -> normalizer
        }
    }

    // ---- normalize and write y (bf16 hi/lo split) ----
    const float inv0 = 1.0f / o[8][0];
    const float inv1 = 1.0f / o[8][2];
#pragma unroll
    for (int nb = 0; nb < 8; nb++) {
        const int col = h * HDIM + nb * 8 + t * 2;
        float a0 = o[nb][0] * inv0, a1 = o[nb][1] * inv0;
        float b0 = o[nb][2] * inv1, b1 = o[nb][3] * inv1;
        uint32_t h0 = packbf(a0, a1);
        uint32_t l0 = packbf(a0 - lo_f(h0), a1 - hi_f(h0));
        uint32_t h1 = packbf(b0, b1);
        uint32_t l1 = packbf(b0 - lo_f(h1), b1 - hi_f(h1));
        *reinterpret_cast<uint32_t*>(yh + (size_t)rowg0 * C_DIM + col) = h0;
        *reinterpret_cast<uint32_t*>(yl + (size_t)rowg0 * C_DIM + col) = l0;
        *reinterpret_cast<uint32_t*>(yh + (size_t)rowg1 * C_DIM + col) = h1;
        *reinterpret_cast<uint32_t*>(yl + (size_t)rowg1 * C_DIM + col) = l1;
    }
}

// ---------------------------------------------------------------------------
// Launch
// ---------------------------------------------------------------------------
extern "C" void kernel_launch(void* const* d_in, const int* in_sizes, int n_in,
                              void* d_out, int out_size)
{
    (void)in_sizes; (void)n_in; (void)out_size;
    const float* x      = (const float*)d_in[0];
    const float* W_qkv  = (const float*)d_in[2];
    const float* b_qkv  = (const float*)d_in[3];
    const float* W_proj = (const float*)d_in[4];
    const float* b_proj = (const float*)d_in[5];
    float* out = (float*)d_out;

    __nv_bfloat16 *xh, *xl, *qkvh, *qkvl, *yh, *yl, *wqh, *wql, *wph, *wpl;
    cudaGetSymbolAddress((void**)&xh, g_xh);
    cudaGetSymbolAddress((void**)&xl, g_xl);
    cudaGetSymbolAddress((void**)&qkvh, g_qkvh);
    cudaGetSymbolAddress((void**)&qkvl, g_qkvl);
    cudaGetSymbolAddress((void**)&yh, g_yh);
    cudaGetSymbolAddress((void**)&yl, g_yl);
    cudaGetSymbolAddress((void**)&wqh, g_wqh);
    cudaGetSymbolAddress((void**)&wql, g_wql);
    cudaGetSymbolAddress((void**)&wph, g_wph);
    cudaGetSymbolAddress((void**)&wpl, g_wpl);

    cudaFuncSetAttribute(gemm_mma,
                         cudaFuncAttributeMaxDynamicSharedMemorySize, GEMM_SMEM);
    cudaFuncSetAttribute(attn_mma,
                         cudaFuncAttributeMaxDynamicSharedMemorySize, ATT_SMEM);

    // 0) prep: weight transpose+split, input split
    transpose_split<<<dim3(QKV3 / 32, C_DIM / 32), 256>>>(
        W_qkv, wqh, wql, C_DIM, QKV3);
    transpose_split<<<dim3(C_DIM / 32, C_DIM / 32), 256>>>(
        W_proj, wph, wpl, C_DIM, C_DIM);
    split_f32<<<(T_SEQ * C_DIM / 4 + 255) / 256, 256>>>(
        x, xh, xl, T_SEQ * C_DIM / 4);

    // 1) qkv: Q -> log2-domain fp16 hi/lo, K/V -> single fp16
    gemm_mma<<<dim3(QKV3 / 256, T_SEQ / 128), 256, GEMM_SMEM>>>(
        xh, xl, wqh, wql, b_qkv, nullptr, qkvh, qkvl, T_SEQ, QKV3, C_DIM, 1);

    // 2) y = causal_attention(qkv) -> bf16 hi/lo   (64-row q-tiles, 2 CTA/SM)
    attn_mma<<<dim3(T_SEQ / 64, NHEAD), 128, ATT_SMEM>>>(qkvh, qkvl, yh, yl);

    // 3) out = y @ W_proj + b_proj (fp32)
    gemm_mma<<<dim3(C_DIM / 256, T_SEQ / 128), 256, GEMM_SMEM>>>(
        yh, yl, wph, wpl, b_proj, out, nullptr, nullptr, T_SEQ, C_DIM, C_DIM, 0);
}

// round 16
// speedup vs baseline: 1.5374x; 1.1607x over previous
#include <cuda_runtime.h>
#include <cuda_bf16.h>
#include <cuda_fp16.h>
#include <math.h>
#include <stdint.h>

// Problem constants
#define T_SEQ 4096
#define C_DIM 768
#define NHEAD 12
#define HDIM  64
#define QKV3  (3 * C_DIM)

// ---------------------------------------------------------------------------
// Scratch (allocation-guard-safe device globals). All 2-byte planes hold fp16
// bits now: x/y/Q = fp16 hi/lo pairs, K/V = fp16 single (hi plane), weights =
// single fp16 (h plane only; l planes retained but unused).
// ---------------------------------------------------------------------------
__device__ __half g_xh[(size_t)T_SEQ * C_DIM];
__device__ __half g_xl[(size_t)T_SEQ * C_DIM];
__device__ __half g_qkvh[(size_t)T_SEQ * QKV3];
__device__ __half g_qkvl[(size_t)T_SEQ * QKV3];
__device__ __half g_yh[(size_t)T_SEQ * C_DIM];
__device__ __half g_yl[(size_t)T_SEQ * C_DIM];
__device__ __half g_wq[(size_t)QKV3 * C_DIM];    // W_qkv^T [3C][C], fp16
__device__ __half g_wp[(size_t)C_DIM * C_DIM];   // W_proj^T [C][C], fp16

// ---------------------------------------------------------------------------
// MMA / ldmatrix / cp.async helpers (sm_80+ PTX; assembles on plain sm_103)
// ---------------------------------------------------------------------------
__device__ __forceinline__ uint32_t smem_u32(const void* p) {
    uint32_t a;
    asm("{ .reg .u64 t; cvta.to.shared.u64 t, %1; cvt.u32.u64 %0, t; }"
        : "=r"(a) : "l"(p));
    return a;
}
__device__ __forceinline__ void mma_f16(float* c, const uint32_t* a,
                                        const uint32_t* b) {
    asm volatile(
        "mma.sync.aligned.m16n8k16.row.col.f32.f16.f16.f32 "
        "{%0,%1,%2,%3}, {%4,%5,%6,%7}, {%8,%9}, {%0,%1,%2,%3};"
        : "+f"(c[0]), "+f"(c[1]), "+f"(c[2]), "+f"(c[3])
        : "r"(a[0]), "r"(a[1]), "r"(a[2]), "r"(a[3]), "r"(b[0]), "r"(b[1]));
}
__device__ __forceinline__ void ldsm_x4(uint32_t* r, uint32_t a) {
    asm volatile("ldmatrix.sync.aligned.m8n8.x4.shared.b16 {%0,%1,%2,%3}, [%4];"
                 : "=r"(r[0]), "=r"(r[1]), "=r"(r[2]), "=r"(r[3]) : "r"(a));
}
__device__ __forceinline__ void ldsm_x4_t(uint32_t* r, uint32_t a) {
    asm volatile("ldmatrix.sync.aligned.m8n8.x4.trans.shared.b16 {%0,%1,%2,%3}, [%4];"
                 : "=r"(r[0]), "=r"(r[1]), "=r"(r[2]), "=r"(r[3]) : "r"(a));
}
__device__ __forceinline__ void cp16(uint32_t dst, const void* src) {
    asm volatile("cp.async.cg.shared.global [%0], [%1], 16;"
                 :: "r"(dst), "l"(src));
}
#define CP_COMMIT() asm volatile("cp.async.commit_group;" ::: "memory")
#define CP_WAIT1()  asm volatile("cp.async.wait_group 1;" ::: "memory")
#define CP_WAIT0()  asm volatile("cp.async.wait_group 0;" ::: "memory")

// pack two f32 -> f16x2 / bf16x2 (first arg -> low half)
__device__ __forceinline__ uint32_t packhf(float lo, float hi) {
    uint32_t d;
    asm("cvt.rn.f16x2.f32 %0, %1, %2;" : "=r"(d) : "f"(hi), "f"(lo));
    return d;
}
__device__ __forceinline__ uint32_t packbf(float lo, float hi) {
    uint32_t d;
    asm("cvt.rn.bf16x2.f32 %0, %1, %2;" : "=r"(d) : "f"(hi), "f"(lo));
    return d;
}
__device__ __forceinline__ float lo_h(uint32_t u) {
    __half2 h = *reinterpret_cast<__half2*>(&u);
    return __half2float(h.x);
}
__device__ __forceinline__ float hi_h(uint32_t u) {
    __half2 h = *reinterpret_cast<__half2*>(&u);
    return __half2float(h.y);
}
__device__ __forceinline__ float ex2f(float x) {
    float y;
    asm("ex2.approx.f32 %0, %1;" : "=f"(y) : "f"(x));
    return y;
}

// byte offset into a [rows][64]-elem(2B) tile with chunk-XOR swizzle (16B)
__device__ __forceinline__ uint32_t sw_off(int row, int chunk) {
    return (uint32_t)((row << 7) + (((chunk ^ row) & 7) << 4) + ((chunk & ~7) << 4));
}

// ---------------------------------------------------------------------------
// Prep: fp32 -> fp16 hi/lo split (float4 granularity)
// ---------------------------------------------------------------------------
__global__ __launch_bounds__(256) void split_f32(
    const float* __restrict__ X, __half* __restrict__ Xh,
    __half* __restrict__ Xl, int n4)
{
    int i = blockIdx.x * 256 + threadIdx.x;
    if (i >= n4) return;
    float4 x = reinterpret_cast<const float4*>(X)[i];
    uint32_t h0 = packhf(x.x, x.y);
    uint32_t h1 = packhf(x.z, x.w);
    uint32_t l0 = packhf(x.x - lo_h(h0), x.y - hi_h(h0));
    uint32_t l1 = packhf(x.z - lo_h(h1), x.w - hi_h(h1));
    reinterpret_cast<uint2*>(Xh)[i] = make_uint2(h0, h1);
    reinterpret_cast<uint2*>(Xl)[i] = make_uint2(l0, l1);
}

// ---------------------------------------------------------------------------
// Prep: W[K][N] -> Wt fp16 [N][K] (transpose + round)
// ---------------------------------------------------------------------------
__global__ __launch_bounds__(256) void transpose_h(
    const float* __restrict__ W, __half* __restrict__ T, int K, int N)
{
    __shared__ float tile[32][33];
    const int tx = threadIdx.x & 31;
    const int ty = threadIdx.x >> 5;
    const int n0 = blockIdx.x * 32;
    const int k0 = blockIdx.y * 32;
#pragma unroll
    for (int i = 0; i < 4; i++)
        tile[ty + 8 * i][tx] = W[(size_t)(k0 + ty + 8 * i) * N + n0 + tx];
    __syncthreads();
#pragma unroll
    for (int i = 0; i < 4; i++)
        T[(size_t)(n0 + ty + 8 * i) * K + k0 + tx] =
            __float2half_rn(tile[tx][ty + 8 * i]);
}

// ---------------------------------------------------------------------------
// 2-term fp16 HMMA GEMM: C = (Ah+Al)[M,K] @ (B[N,K])^T + bias.
// A = activations fp16 hi/lo (exact to 2^-24), B = weights single fp16.
// CTA 128x256, warp tile 64x64 (2m x 4n), k-chunk 64, 2-stage cp.async
// (64KB/stage). mode=1 (QKV): Q cols -> fp16 hi/lo * QSCALE; K/V -> fp16.
// mode=0: fp32 out.
// ---------------------------------------------------------------------------
#define GEMM_STAGE 65536
#define GEMM_SMEM (2 * GEMM_STAGE)
#define QSCALE 0.18033688011112042f   // 0.125 * log2(e)

__global__ __launch_bounds__(256) void gemm_mma(
    const __half* __restrict__ Ah, const __half* __restrict__ Al,
    const __half* __restrict__ B,
    const float* __restrict__ bias, float* __restrict__ Cf,
    __half* __restrict__ Ch, __half* __restrict__ Cl,
    int M, int N, int K, int mode)
{
    extern __shared__ char smb[];
    const uint32_t ubase = smem_u32(smb);

    const int tid = threadIdx.x;
    const int w = tid >> 5, lane = tid & 31;
    const int g = lane >> 2, t = lane & 3;
    const int wm = w & 1, wn = w >> 1;       // 2 m-strips x 4 n-strips
    const int by = blockIdx.y, bx = blockIdx.x;

    float acc[4][8][4];
#pragma unroll
    for (int mi = 0; mi < 4; mi++)
#pragma unroll
        for (int nb = 0; nb < 8; nb++)
#pragma unroll
            for (int c = 0; c < 4; c++) acc[mi][nb][c] = 0.0f;

    const int a_row = (lane & 15);
    const int a_chs = (lane >> 4);
    const int b_row = (lane & 7) + ((lane >> 4) << 3);
    const int b_chs = (lane >> 3) & 1;

    const int NI = K / 64;

    // stage layout: Ah 0 (16KB) | Al 16K (16KB) | B 32K (32KB)
    auto load_stage = [&](int st, int k0) {
        const uint32_t ub = ubase + st * GEMM_STAGE;
#pragma unroll
        for (int j = 0; j < 4; j++) {         // A: 128 rows x 8 chunks
            const int i = tid + 256 * j;
            const int row = i >> 3, ch = i & 7;
            const size_t ga = (size_t)(by * 128 + row) * K + k0 + ch * 8;
            const uint32_t so = sw_off(row, ch);
            cp16(ub + so, Ah + ga);
            cp16(ub + 16384 + so, Al + ga);
        }
#pragma unroll
        for (int j = 0; j < 8; j++) {         // B: 256 rows x 8 chunks
            const int i = tid + 256 * j;
            const int row = i >> 3, ch = i & 7;
            const size_t gb = (size_t)(bx * 256 + row) * K + k0 + ch * 8;
            cp16(ub + 32768 + sw_off(row, ch), B + gb);
        }
    };

    load_stage(0, 0);
    CP_COMMIT();

    for (int it = 0; it < NI; it++) {
        const int st = it & 1;
        CP_WAIT0();
        __syncthreads();
        if (it + 1 < NI) {
            load_stage(st ^ 1, (it + 1) * 64);
            CP_COMMIT();
        }

        const uint32_t uAh = ubase + st * GEMM_STAGE;
        const uint32_t uAl = uAh + 16384;
        const uint32_t uB  = uAh + 32768;

#pragma unroll
        for (int ks = 0; ks < 4; ks++) {
            uint32_t ah[4][4], al[4][4];
#pragma unroll
            for (int mi = 0; mi < 4; mi++) {
                const uint32_t so = sw_off(wm * 64 + mi * 16 + a_row, 2 * ks + a_chs);
                ldsm_x4(ah[mi], uAh + so);
                ldsm_x4(al[mi], uAl + so);
            }
#pragma unroll
            for (int nb = 0; nb < 8; nb += 2) {
                uint32_t b4[4];
                const uint32_t so = sw_off(wn * 64 + nb * 8 + b_row, 2 * ks + b_chs);
                ldsm_x4(b4, uB + so);
#pragma unroll
                for (int mi = 0; mi < 4; mi++) {
                    mma_f16(acc[mi][nb], ah[mi], b4);
                    mma_f16(acc[mi][nb], al[mi], b4);
                    mma_f16(acc[mi][nb + 1], ah[mi], b4 + 2);
                    mma_f16(acc[mi][nb + 1], al[mi], b4 + 2);
                }
            }
        }
    }

    // Epilogue
    const bool q_region = (mode == 1) && (bx * 256 < C_DIM);   // Q -> fp16 hi/lo
#pragma unroll
    for (int mi = 0; mi < 4; mi++) {
#pragma unroll
        for (int nb = 0; nb < 8; nb++) {
            const int row = by * 128 + wm * 64 + mi * 16 + g;
            const int col = bx * 256 + wn * 64 + nb * 8 + t * 2;
            const float2 bb = *reinterpret_cast<const float2*>(bias + col);
            float v0 = acc[mi][nb][0] + bb.x;
            float v1 = acc[mi][nb][1] + bb.y;
            float v2 = acc[mi][nb][2] + bb.x;
            float v3 = acc[mi][nb][3] + bb.y;
            if (mode) {
                if (q_region) {
                    v0 *= QSCALE; v1 *= QSCALE; v2 *= QSCALE; v3 *= QSCALE;
                    uint32_t h0 = packhf(v0, v1);
                    uint32_t l0 = packhf(v0 - lo_h(h0), v1 - hi_h(h0));
                    uint32_t h1 = packhf(v2, v3);
                    uint32_t l1 = packhf(v2 - lo_h(h1), v3 - hi_h(h1));
                    *reinterpret_cast<uint32_t*>(Ch + (size_t)row * N + col) = h0;
                    *reinterpret_cast<uint32_t*>(Cl + (size_t)row * N + col) = l0;
                    *reinterpret_cast<uint32_t*>(Ch + (size_t)(row + 8) * N + col) = h1;
                    *reinterpret_cast<uint32_t*>(Cl + (size_t)(row + 8) * N + col) = l1;
                } else {
                    // K/V: single fp16 (hi plane only)
                    *reinterpret_cast<uint32_t*>(Ch + (size_t)row * N + col) =
                        packhf(v0, v1);
                    *reinterpret_cast<uint32_t*>(Ch + (size_t)(row + 8) * N + col) =
                        packhf(v2, v3);
                }
            } else {
                *reinterpret_cast<float2*>(Cf + (size_t)row * N + col) =
                    make_float2(v0, v1);
                *reinterpret_cast<float2*>(Cf + (size_t)(row + 8) * N + col) =
                    make_float2(v2, v3);
            }
        }
    }
}

// ---------------------------------------------------------------------------
// Flash attention v4: 128-thread CTA (4 warps), q-tile 64 rows, 2 CTAs/SM.
// All-fp16 operands: Q fp16 hi/lo (2-term S), K fp16 single, V fp16 single
// (1-term PV + ones-column normalizer). 3-stage cp.async K/V pipeline
// (32KB/stage), exp2-domain softmax.
// SMEM: Q 16KB + 3 x 32KB = 112KB -> 2 CTAs/SM.
// ---------------------------------------------------------------------------
#define ATT_STAGE 32768
#define ATT_SMEM (16384 + 3 * ATT_STAGE)
#define ONES_F16X2 0x3C003C00u

__global__ __launch_bounds__(128, 2) void attn_mma(
    const __half* __restrict__ qkvh, const __half* __restrict__ qkvl,
    __half* __restrict__ yh, __half* __restrict__ yl)
{
    extern __shared__ char smb[];
    const uint32_t uQh = smem_u32(smb);
    const uint32_t uQl = uQh + 8192;
    const uint32_t uKV = uQh + 16384;   // stage s: +s*ATT_STAGE (Kh|Vh)

    const int qb = 63 - (int)blockIdx.x;   // 64-row q-block, long CTAs first
    const int h = blockIdx.y;
    const int tid = threadIdx.x;
    const int w = tid >> 5, lane = tid & 31;
    const int g = lane >> 2, t = lane & 3;
    const int r0 = w * 16;

    const int nkb = (qb * 64 + 63) / 128 + 1;

    const size_t qoff = (size_t)h * HDIM;
    const size_t koff = C_DIM + (size_t)h * HDIM;
    const size_t voff = 2 * C_DIM + (size_t)h * HDIM;

    auto load_kv = [&](int st, int kb) {
        const uint32_t ub = uKV + st * ATT_STAGE;
#pragma unroll
        for (int j = 0; j < 8; j++) {
            const int i = tid + 128 * j;
            const int row = i >> 3, ch = i & 7;
            const size_t gk = (size_t)(kb * 128 + row) * QKV3 + koff + ch * 8;
            const size_t gv = (size_t)(kb * 128 + row) * QKV3 + voff + ch * 8;
            const uint32_t so = sw_off(row, ch);
            cp16(ub + so, qkvh + gk);
            cp16(ub + 16384 + so, qkvh + gv);
        }
    };

    // Prefetch K/V blocks 0,1, then load Q (64 rows) while the DMA drains
    load_kv(0, 0);
    CP_COMMIT();
    if (nkb > 1) {
        load_kv(1, 1);
        CP_COMMIT();
    }
#pragma unroll 4
    for (int i = tid; i < 512; i += 128) {
        const int row = i >> 3, ch = i & 7;
        const size_t gq = (size_t)(qb * 64 + row) * QKV3 + qoff + ch * 8;
        const uint32_t so = sw_off(row, ch);
        *reinterpret_cast<uint4*>(smb + so) =
            *reinterpret_cast<const uint4*>(qkvh + gq);
        *reinterpret_cast<uint4*>(smb + 8192 + so) =
            *reinterpret_cast<const uint4*>(qkvl + gq);
    }
    __syncthreads();

    // Q fragments (fp16 hi/lo, registers for the whole kernel); log2 domain
    uint32_t qfh[4][4], qfl[4][4];
    {
        const int arow = r0 + (lane & 15);
        const int achs = (lane >> 4);
#pragma unroll
        for (int ks = 0; ks < 4; ks++) {
            ldsm_x4(qfh[ks], uQh + sw_off(arow, 2 * ks + achs));
            ldsm_x4(qfl[ks], uQl + sw_off(arow, 2 * ks + achs));
        }
    }

    // o[0..7] = output dims; o[8] = softmax normalizer (ones-column block)
    float o[9][4];
#pragma unroll
    for (int nb = 0; nb < 9; nb++)
#pragma unroll
        for (int c = 0; c < 4; c++) o[nb][c] = 0.0f;
    float m0r = -INFINITY, m1r = -INFINITY;

    const uint32_t ones2[2] = { ONES_F16X2, ONES_F16X2 };

    const int b_row = (lane & 7) + ((lane >> 4) << 3);
    const int b_chs = (lane >> 3) & 1;
    const int v_row = (lane & 7) + (((lane >> 3) & 1) << 3);
    const int v_chs = (lane >> 4);

    const int rowg0 = qb * 64 + r0 + g;
    const int rowg1 = rowg0 + 8;

    for (int kb = 0; kb < nkb; kb++) {
        const int st = kb % 3;
        if (kb + 1 < nkb) CP_WAIT1(); else CP_WAIT0();
        __syncthreads();

        if (kb + 2 < nkb) {
            load_kv((kb + 2) % 3, kb + 2);
            CP_COMMIT();
        }

        const uint32_t uKh = uKV + st * ATT_STAGE;
        const uint32_t uVh = uKh + 16384;

        // ---- S = Q @ K^T : Qh/Ql fp16 x K fp16 (2-term, log2 domain) ----
        float s[16][4];
#pragma unroll
        for (int nb = 0; nb < 16; nb++)
#pragma unroll
            for (int c = 0; c < 4; c++) s[nb][c] = 0.0f;

#pragma unroll
        for (int nb = 0; nb < 16; nb += 2) {
#pragma unroll
            for (int ks = 0; ks < 4; ks++) {
                uint32_t kh4[4];
                const uint32_t so = sw_off(nb * 8 + b_row, 2 * ks + b_chs);
                ldsm_x4(kh4, uKh + so);
                mma_f16(s[nb], qfh[ks], kh4);
                mma_f16(s[nb], qfl[ks], kh4);
                mma_f16(s[nb + 1], qfh[ks], kh4 + 2);
                mma_f16(s[nb + 1], qfl[ks], kh4 + 2);
            }
        }

        // ---- causal mask on the last key block (global indices) ----
        if (kb == nkb - 1) {
#pragma unroll
            for (int nb = 0; nb < 16; nb++) {
                const int keyg = kb * 128 + nb * 8 + t * 2;
                if (keyg > rowg0)     s[nb][0] = -1e30f;
                if (keyg + 1 > rowg0) s[nb][1] = -1e30f;
                if (keyg > rowg1)     s[nb][2] = -1e30f;
                if (keyg + 1 > rowg1) s[nb][3] = -1e30f;
            }
        }

        // ---- online softmax max-phase (rows g / g+8) ----
        float mx0 = -INFINITY, mx1 = -INFINITY;
#pragma unroll
        for (int nb = 0; nb < 16; nb++) {
            mx0 = fmaxf(mx0, fmaxf(s[nb][0], s[nb][1]));
            mx1 = fmaxf(mx1, fmaxf(s[nb][2], s[nb][3]));
        }
        mx0 = fmaxf(mx0, __shfl_xor_sync(0xffffffffu, mx0, 1));
        mx0 = fmaxf(mx0, __shfl_xor_sync(0xffffffffu, mx0, 2));
        mx1 = fmaxf(mx1, __shfl_xor_sync(0xffffffffu, mx1, 1));
        mx1 = fmaxf(mx1, __shfl_xor_sync(0xffffffffu, mx1, 2));
        const float mn0 = fmaxf(m0r, mx0);
        const float mn1 = fmaxf(m1r, mx1);
        const float c0 = ex2f(m0r - mn0);
        const float c1 = ex2f(m1r - mn1);
        m0r = mn0; m1r = mn1;
#pragma unroll
        for (int nb = 0; nb < 9; nb++) {
            o[nb][0] *= c0; o[nb][1] *= c0;
            o[nb][2] *= c1; o[nb][3] *= c1;
        }

        // ---- ex2 + pack + PV per kk chunk (P fp16, V fp16, + ones col) ----
#pragma unroll
        for (int kk = 0; kk < 8; kk++) {
            uint32_t pf[4];
            {
                const float e0 = ex2f(s[2 * kk][0] - mn0);
                const float e1 = ex2f(s[2 * kk][1] - mn0);
                const float e2 = ex2f(s[2 * kk][2] - mn1);
                const float e3 = ex2f(s[2 * kk][3] - mn1);
                pf[0] = packhf(e0, e1);
                pf[1] = packhf(e2, e3);
                const float f0 = ex2f(s[2 * kk + 1][0] - mn0);
                const float f1 = ex2f(s[2 * kk + 1][1] - mn0);
                const float f2 = ex2f(s[2 * kk + 1][2] - mn1);
                const float f3 = ex2f(s[2 * kk + 1][3] - mn1);
                pf[2] = packhf(f0, f1);
                pf[3] = packhf(f2, f3);
            }
#pragma unroll
            for (int nb = 0; nb < 8; nb += 2) {
                uint32_t vh4[4];
                const uint32_t so = sw_off(kk * 16 + v_row, nb + v_chs);
                ldsm_x4_t(vh4, uVh + so);
                mma_f16(o[nb], pf, vh4);
                mma_f16(o[nb + 1], pf, vh4 + 2);
            }
            mma_f16(o[8], pf, ones2);   // row sums of P -> normalizer
        }
    }

    // ---- normalize and write y (fp16 hi/lo split for gemm2's A operand) ----
    const float inv0 = 1.0f / o[8][0];
    const float inv1 = 1.0f / o[8][2];
#pragma unroll
    for (int nb = 0; nb < 8; nb++) {
        const int col = h * HDIM + nb * 8 + t * 2;
        float a0 = o[nb][0] * inv0, a1 = o[nb][1] * inv0;
        float b0 = o[nb][2] * inv1, b1 = o[nb][3] * inv1;
        uint32_t h0 = packhf(a0, a1);
        uint32_t l0 = packhf(a0 - lo_h(h0), a1 - hi_h(h0));
        uint32_t h1 = packhf(b0, b1);
        uint32_t l1 = packhf(b0 - lo_h(h1), b1 - hi_h(h1));
        *reinterpret_cast<uint32_t*>(yh + (size_t)rowg0 * C_DIM + col) = h0;
        *reinterpret_cast<uint32_t*>(yl + (size_t)rowg0 * C_DIM + col) = l0;
        *reinterpret_cast<uint32_t*>(yh + (size_t)rowg1 * C_DIM + col) = h1;
        *reinterpret_cast<uint32_t*>(yl + (size_t)rowg1 * C_DIM + col) = l1;
    }
}

// ---------------------------------------------------------------------------
// Launch
// ---------------------------------------------------------------------------
extern "C" void kernel_launch(void* const* d_in, const int* in_sizes, int n_in,
                              void* d_out, int out_size)
{
    (void)in_sizes; (void)n_in; (void)out_size;
    const float* x      = (const float*)d_in[0];
    const float* W_qkv  = (const float*)d_in[2];
    const float* b_qkv  = (const float*)d_in[3];
    const float* W_proj = (const float*)d_in[4];
    const float* b_proj = (const float*)d_in[5];
    float* out = (float*)d_out;

    __half *xh, *xl, *qkvh, *qkvl, *yh, *yl, *wq, *wp;
    cudaGetSymbolAddress((void**)&xh, g_xh);
    cudaGetSymbolAddress((void**)&xl, g_xl);
    cudaGetSymbolAddress((void**)&qkvh, g_qkvh);
    cudaGetSymbolAddress((void**)&qkvl, g_qkvl);
    cudaGetSymbolAddress((void**)&yh, g_yh);
    cudaGetSymbolAddress((void**)&yl, g_yl);
    cudaGetSymbolAddress((void**)&wq, g_wq);
    cudaGetSymbolAddress((void**)&wp, g_wp);

    cudaFuncSetAttribute(gemm_mma,
                         cudaFuncAttributeMaxDynamicSharedMemorySize, GEMM_SMEM);
    cudaFuncSetAttribute(attn_mma,
                         cudaFuncAttributeMaxDynamicSharedMemorySize, ATT_SMEM);

    // 0) prep: weight transpose (fp16), input split (fp16 hi/lo)
    transpose_h<<<dim3(QKV3 / 32, C_DIM / 32), 256>>>(W_qkv, wq, C_DIM, QKV3);
    transpose_h<<<dim3(C_DIM / 32, C_DIM / 32), 256>>>(W_proj, wp, C_DIM, C_DIM);
    split_f32<<<(T_SEQ * C_DIM / 4 + 255) / 256, 256>>>(
        x, xh, xl, T_SEQ * C_DIM / 4);

    // 1) qkv: Q -> log2-domain fp16 hi/lo, K/V -> single fp16
    gemm_mma<<<dim3(QKV3 / 256, T_SEQ / 128), 256, GEMM_SMEM>>>(
        xh, xl, wq, b_qkv, nullptr, qkvh, qkvl, T_SEQ, QKV3, C_DIM, 1);

    // 2) y = causal_attention(qkv) -> fp16 hi/lo   (64-row q-tiles, 2 CTA/SM)
    attn_mma<<<dim3(T_SEQ / 64, NHEAD), 128, ATT_SMEM>>>(qkvh, qkvl, yh, yl);

    // 3) out = y @ W_proj + b_proj (fp32)
    gemm_mma<<<dim3(C_DIM / 256, T_SEQ / 128), 256, GEMM_SMEM>>>(
        yh, yl, wp, b_proj, out, nullptr, nullptr, T_SEQ, C_DIM, C_DIM, 0);
}